// round 1
// baseline (speedup 1.0000x reference)
#include <cuda_runtime.h>
#include <cstddef>

// ----------------------------------------------------------------------------
// Problem constants
// ----------------------------------------------------------------------------
#define NB 1024            // batch
#define R 116              // ROIs
#define RR (R * R)         // 13456
#define LAYERS 4
#define FEAT 2320          // R*4*(L+1)
#define HID 1024
#define MAXDB 32768
#define EPS 1e-5f

// ----------------------------------------------------------------------------
// Device scratch (static allocation only — no cudaMalloc allowed)
// ----------------------------------------------------------------------------
__device__ __align__(16) float g_Z  [(size_t)NB * RR];
__device__ __align__(16) float g_att[(size_t)NB * RR];
__device__ __align__(16) float g_Vt [(size_t)NB * RR];
__device__ __align__(16) float g_S  [(size_t)NB * RR];
__device__ __align__(16) float g_T  [(size_t)NB * RR];
__device__ __align__(16) float g_Z1 [(size_t)NB * RR];
__device__ __align__(16) float g_X  [NB * R * 3];
__device__ __align__(16) float g_X1 [NB * R * 3];
__device__ __align__(16) float g_XZ [(size_t)NB * FEAT];
__device__ __align__(16) float g_H  [(size_t)NB * HID];
__device__ float g_ps[R * NB];       // per-(channel, batch) partial sums
__device__ float g_pq[R * NB];       // per-(channel, batch) partial sq-sums
__device__ float g_scale[R];
__device__ float g_shift[R];
__device__ float g_dpart[2 * MAXDB]; // down-sample partials
__device__ float g_dss[2];           // down-sample scale/shift

__device__ __forceinline__ float wsum(float v) {
#pragma unroll
    for (int o = 16; o; o >>= 1) v += __shfl_xor_sync(0xffffffffu, v, o);
    return v;
}

// ----------------------------------------------------------------------------
// Generic copy
// ----------------------------------------------------------------------------
__global__ void k_copy(const float* __restrict__ src, float* __restrict__ dst, size_t n) {
    size_t i = (size_t)blockIdx.x * blockDim.x + threadIdx.x;
    if (i < n) dst[i] = src[i];
}

// ----------------------------------------------------------------------------
// Tiled SGEMM.
//  KMAJ=true : C[i,j] = sum_k A[i*lda+k] * B[j*ldb+k]     (NT)
//  KMAJ=false: C[i,j] = sum_k A[k*lda+i] * B[k*ldb+j]     (TN)
// Optional per-column bias, optional relu. Batched via blockIdx.z.
// ----------------------------------------------------------------------------
template <int BM, int BN, int TM, int TN, bool KMAJ>
__global__ void __launch_bounds__((BM / TM) * (BN / TN), 2)
k_gemm(const float* __restrict__ A, const float* __restrict__ Bm,
       const float* __restrict__ bias, float* __restrict__ C,
       int M, int N, int K, int lda, int ldb, int ldc,
       size_t sA, size_t sB, size_t sC, int do_relu)
{
    constexpr int BK = 8;
    static_assert((BM / TM) * (BN / TN) == 256, "256 threads expected");
    static_assert(BM == 128, "loader assumes BM=128");
    __shared__ float As[BK][BM + 4];
    __shared__ float Bs[BK][BN + 4];
    const int tid = threadIdx.x;
    constexpr int BNT = BN / TN;
    const int tx = tid % BNT;
    const int ty = tid / BNT;
    const int rowBase = blockIdx.y * BM;
    const int colBase = blockIdx.x * BN;
    const float* Ab = A + (size_t)blockIdx.z * sA;
    const float* Bb = Bm + (size_t)blockIdx.z * sB;

    float acc[TM][TN];
#pragma unroll
    for (int i = 0; i < TM; i++)
#pragma unroll
        for (int j = 0; j < TN; j++) acc[i][j] = 0.f;

    for (int k0 = 0; k0 < K; k0 += BK) {
        // ---- A tile ----
        if constexpr (KMAJ) {
            const int i = tid >> 1;
            const int kg = k0 + (tid & 1) * 4;
            const int r = rowBase + i;
            float4 v = make_float4(0.f, 0.f, 0.f, 0.f);
            if (r < M && kg < K)
                v = *reinterpret_cast<const float4*>(Ab + (size_t)r * lda + kg);
            const int kk = (tid & 1) * 4;
            As[kk + 0][i] = v.x; As[kk + 1][i] = v.y;
            As[kk + 2][i] = v.z; As[kk + 3][i] = v.w;
        } else {
            const int kk = tid >> 5;
            const int i4 = (tid & 31) << 2;
            const int kg = k0 + kk;
            const int r = rowBase + i4;
            float4 v = make_float4(0.f, 0.f, 0.f, 0.f);
            if (kg < K && r + 3 < M)
                v = *reinterpret_cast<const float4*>(Ab + (size_t)kg * lda + r);
            *reinterpret_cast<float4*>(&As[kk][i4]) = v;
        }
        // ---- B tile ----
        if constexpr (KMAJ) {
            const int j = tid >> 1;
            if (j < BN) {
                const int kg = k0 + (tid & 1) * 4;
                const int c = colBase + j;
                float4 v = make_float4(0.f, 0.f, 0.f, 0.f);
                if (c < N && kg < K)
                    v = *reinterpret_cast<const float4*>(Bb + (size_t)c * ldb + kg);
                const int kk = (tid & 1) * 4;
                Bs[kk + 0][j] = v.x; Bs[kk + 1][j] = v.y;
                Bs[kk + 2][j] = v.z; Bs[kk + 3][j] = v.w;
            }
        } else {
            constexpr int PR = BN / 4;
            const int kk = tid / PR;
            const int j4 = (tid % PR) << 2;
            if (kk < BK) {
                const int kg = k0 + kk;
                const int c = colBase + j4;
                float4 v = make_float4(0.f, 0.f, 0.f, 0.f);
                if (kg < K && c + 3 < N)
                    v = *reinterpret_cast<const float4*>(Bb + (size_t)kg * ldb + c);
                *reinterpret_cast<float4*>(&Bs[kk][j4]) = v;
            }
        }
        __syncthreads();
#pragma unroll
        for (int kk = 0; kk < BK; kk++) {
            float af[TM], bf[TN];
#pragma unroll
            for (int i = 0; i < TM; i++) af[i] = As[kk][ty * TM + i];
#pragma unroll
            for (int j = 0; j < TN; j++) bf[j] = Bs[kk][tx * TN + j];
#pragma unroll
            for (int i = 0; i < TM; i++)
#pragma unroll
                for (int j = 0; j < TN; j++)
                    acc[i][j] = fmaf(af[i], bf[j], acc[i][j]);
        }
        __syncthreads();
    }

    float* Cb = C + (size_t)blockIdx.z * sC;
#pragma unroll
    for (int i = 0; i < TM; i++) {
        const int r = rowBase + ty * TM + i;
        if (r >= M) continue;
#pragma unroll
        for (int j = 0; j < TN; j++) {
            const int c = colBase + tx * TN + j;
            if (c >= N) continue;
            float v = acc[i][j];
            if (bias) v += bias[c];
            if (do_relu) v = fmaxf(v, 0.f);
            Cb[(size_t)r * ldc + c] = v;
        }
    }
}

// ----------------------------------------------------------------------------
// Attention: K = aw1@X^T + ab1 (3xR), scores = K^T K, row softmax -> g_att
// grid = NB, block = 128 (warp-per-row)
// ----------------------------------------------------------------------------
__global__ void k_att(const float* __restrict__ aw1, const float* __restrict__ ab1) {
    __shared__ float Ks[R][3];
    const int b = blockIdx.x;
    const int tid = threadIdx.x;
    const float* Xb = g_X + (size_t)b * (R * 3);
    if (tid < R) {
        const float x0 = Xb[tid * 3 + 0], x1 = Xb[tid * 3 + 1], x2 = Xb[tid * 3 + 2];
#pragma unroll
        for (int o = 0; o < 3; o++)
            Ks[tid][o] = fmaf(aw1[o * 3 + 0], x0,
                         fmaf(aw1[o * 3 + 1], x1,
                         fmaf(aw1[o * 3 + 2], x2, ab1[o])));
    }
    __syncthreads();
    const int w = tid >> 5, lane = tid & 31;
    for (int n = w; n < R; n += 4) {
        const float k0 = Ks[n][0], k1 = Ks[n][1], k2 = Ks[n][2];
        float s[4];
        float mx = -3.0e38f;
#pragma unroll
        for (int it = 0; it < 4; it++) {
            const int m = it * 32 + lane;
            float v = -3.0e38f;
            if (m < R) v = k0 * Ks[m][0] + k1 * Ks[m][1] + k2 * Ks[m][2];
            s[it] = v;
            mx = fmaxf(mx, v);
        }
#pragma unroll
        for (int o = 16; o; o >>= 1) mx = fmaxf(mx, __shfl_xor_sync(0xffffffffu, mx, o));
        float sum = 0.f, e[4];
#pragma unroll
        for (int it = 0; it < 4; it++) {
            const int m = it * 32 + lane;
            e[it] = (m < R) ? __expf(s[it] - mx) : 0.f;
            sum += e[it];
        }
        sum = wsum(sum);
        const float inv = 1.f / sum;
        float* arow = g_att + ((size_t)b * R + n) * R;
#pragma unroll
        for (int it = 0; it < 4; it++) {
            const int m = it * 32 + lane;
            if (m < R) arow[m] = e[it] * inv;
        }
    }
}

// ----------------------------------------------------------------------------
// X path: XT = S^T @ X (Rx3), X1 = XT @ nw^T + nb; BN partials per (n,b).
// grid = NB, block = 128
// ----------------------------------------------------------------------------
__global__ void k_xpath(const float* __restrict__ nw, const float* __restrict__ nb_) {
    const int b = blockIdx.x;
    __shared__ float Xs[R * 3];
    const float* Xb = g_X + (size_t)b * (R * 3);
    for (int i = threadIdx.x; i < R * 3; i += 128) Xs[i] = Xb[i];
    __syncthreads();
    const int n = threadIdx.x;
    if (n >= R) return;
    float a0 = 0.f, a1 = 0.f, a2 = 0.f;
    const float* Sb = g_S + (size_t)b * RR + n;
    for (int m = 0; m < R; m++) {
        const float s = Sb[(size_t)m * R];
        a0 = fmaf(s, Xs[m * 3 + 0], a0);
        a1 = fmaf(s, Xs[m * 3 + 1], a1);
        a2 = fmaf(s, Xs[m * 3 + 2], a2);
    }
    float ps = 0.f, pq = 0.f;
    float* dst = g_X1 + (size_t)b * (R * 3) + n * 3;
#pragma unroll
    for (int o = 0; o < 3; o++) {
        const float v = fmaf(nw[o * 3 + 0], a0,
                        fmaf(nw[o * 3 + 1], a1,
                        fmaf(nw[o * 3 + 2], a2, nb_[o])));
        dst[o] = v;
        ps += v;
        pq = fmaf(v, v, pq);
    }
    g_ps[n * NB + b] = ps;
    g_pq[n * NB + b] = pq;
}

// ----------------------------------------------------------------------------
// Z1 BN partials: per (b,n) sum over c. grid = NB, block = 128
// ----------------------------------------------------------------------------
__global__ void k_zstats() {
    const int b = blockIdx.x;
    const int w = threadIdx.x >> 5, lane = threadIdx.x & 31;
    for (int n = w; n < R; n += 4) {
        const float* row = g_Z1 + ((size_t)b * R + n) * R;
        float s = 0.f, q = 0.f;
        for (int c = lane; c < R; c += 32) {
            const float v = row[c];
            s += v;
            q = fmaf(v, v, q);
        }
        s = wsum(s);
        q = wsum(q);
        if (lane == 0) { g_ps[n * NB + b] = s; g_pq[n * NB + b] = q; }
    }
}

// Channel reduce: grid = R, block = 256 -> g_scale/g_shift
__global__ void k_reduce_chan(float invcnt, const float* __restrict__ gp,
                              const float* __restrict__ bp) {
    const int n = blockIdx.x;
    float s = 0.f, q = 0.f;
    for (int b = threadIdx.x; b < NB; b += 256) {
        s += g_ps[n * NB + b];
        q += g_pq[n * NB + b];
    }
    __shared__ float shs[8], shq[8];
    s = wsum(s); q = wsum(q);
    const int w = threadIdx.x >> 5, lane = threadIdx.x & 31;
    if (lane == 0) { shs[w] = s; shq[w] = q; }
    __syncthreads();
    if (w == 0) {
        s = (lane < 8) ? shs[lane] : 0.f;
        q = (lane < 8) ? shq[lane] : 0.f;
        s = wsum(s); q = wsum(q);
        if (lane == 0) {
            const float mean = s * invcnt;
            const float var = q * invcnt - mean * mean;
            const float rstd = rsqrtf(var + EPS);
            const float sc = rstd * gp[n];
            g_scale[n] = sc;
            g_shift[n] = bp[n] - mean * sc;
        }
    }
}

// Z <- relu(bn(Z1)) + Z. grid (R, NB), block 128
__global__ void k_zapply() {
    const int n = blockIdx.x, b = blockIdx.y, c = threadIdx.x;
    if (c >= R) return;
    const float sc = g_scale[n], sh = g_shift[n];
    const size_t o = ((size_t)b * R + n) * R + c;
    const float y = fmaf(g_Z1[o], sc, sh);
    g_Z[o] += fmaxf(y, 0.f);
}

// X <- relu(bn(X1)) + X.
__global__ void k_xapply() {
    const int idx = blockIdx.x * 256 + threadIdx.x;
    if (idx >= NB * R * 3) return;
    const int n = (idx / 3) % R;
    const float y = fmaf(g_X1[idx], g_scale[n], g_shift[n]);
    g_X[idx] += fmaxf(y, 0.f);
}

// ----------------------------------------------------------------------------
// down_node: f = relu(X.w + b) per (b,r), raw into slab + per-block partials.
// grid = 928, block = 128 (exactly B*R threads)
// ----------------------------------------------------------------------------
__global__ void k_down_node(const float* __restrict__ w, const float* __restrict__ bp,
                            int off) {
    const int idx = blockIdx.x * 128 + threadIdx.x;
    const float* x = g_X + (size_t)idx * 3;
    const float f = fmaxf(fmaf(x[0], w[0], fmaf(x[1], w[1], fmaf(x[2], w[2], bp[0]))), 0.f);
    const int b = idx / R, r = idx - b * R;
    g_XZ[(size_t)b * FEAT + off + r] = f;
    float s = wsum(f);
    float q = wsum(f * f);
    __shared__ float sh[8];
    const int wr = threadIdx.x >> 5, lane = threadIdx.x & 31;
    if (lane == 0) { sh[wr] = s; sh[4 + wr] = q; }
    __syncthreads();
    if (threadIdx.x == 0) {
        g_dpart[blockIdx.x] = sh[0] + sh[1] + sh[2] + sh[3];
        g_dpart[MAXDB + blockIdx.x] = sh[4] + sh[5] + sh[6] + sh[7];
    }
}

// ----------------------------------------------------------------------------
// down_edge: 3 strided-window dots per Z row (conv1d k=78,s=39,p=39).
// grid = 29696 (warp-per-row x4), block = 128
// ----------------------------------------------------------------------------
__global__ void k_down_edge(const float* __restrict__ w, const float* __restrict__ bp,
                            int off) {
    const int rowid = blockIdx.x * 4 + (threadIdx.x >> 5);
    const int lane = threadIdx.x & 31;
    const float* z = g_Z + (size_t)rowid * R;
    float f0 = 0.f, f1 = 0.f, f2 = 0.f;
    for (int j = lane; j < 78; j += 32) f1 = fmaf(z[j], w[j], f1);
    for (int j = lane; j < 39; j += 32) f0 = fmaf(z[j], w[39 + j], f0);
    for (int j = lane; j < 77; j += 32) f2 = fmaf(z[39 + j], w[j], f2);
    f0 = wsum(f0); f1 = wsum(f1); f2 = wsum(f2);
    float s = 0.f, q = 0.f;
    if (lane == 0) {
        const float bb = bp[0];
        f0 = fmaxf(f0 + bb, 0.f);
        f1 = fmaxf(f1 + bb, 0.f);
        f2 = fmaxf(f2 + bb, 0.f);
        const int b = rowid / R, r = rowid - (rowid / R) * R;
        float* dst = g_XZ + (size_t)b * FEAT + off + r * 3;
        dst[0] = f0; dst[1] = f1; dst[2] = f2;
        s = f0 + f1 + f2;
        q = f0 * f0 + f1 * f1 + f2 * f2;
    }
    __shared__ float sh[8];
    const int wr = threadIdx.x >> 5;
    if (lane == 0) { sh[wr] = s; sh[4 + wr] = q; }
    __syncthreads();
    if (threadIdx.x == 0) {
        g_dpart[blockIdx.x] = sh[0] + sh[1] + sh[2] + sh[3];
        g_dpart[MAXDB + blockIdx.x] = sh[4] + sh[5] + sh[6] + sh[7];
    }
}

// Reduce down-sample partials -> scalar scale/shift. grid=1, block=1024
__global__ void k_dreduce(int nblk, float invcnt, const float* __restrict__ gp,
                          const float* __restrict__ bp) {
    float s = 0.f, q = 0.f;
    for (int i = threadIdx.x; i < nblk; i += 1024) {
        s += g_dpart[i];
        q += g_dpart[MAXDB + i];
    }
    __shared__ float shs[32], shq[32];
    s = wsum(s); q = wsum(q);
    const int w = threadIdx.x >> 5, lane = threadIdx.x & 31;
    if (lane == 0) { shs[w] = s; shq[w] = q; }
    __syncthreads();
    if (w == 0) {
        s = shs[lane];
        q = shq[lane];
        s = wsum(s); q = wsum(q);
        if (lane == 0) {
            const float mean = s * invcnt;
            const float var = q * invcnt - mean * mean;
            const float rstd = rsqrtf(var + EPS);
            const float sc = rstd * gp[0];
            g_dss[0] = sc;
            g_dss[1] = bp[0] - mean * sc;
        }
    }
}

// Normalize slab region in place (width = R or 3R; counts divide exactly).
__global__ void k_dapply(int off, int width) {
    const int idx = blockIdx.x * 256 + threadIdx.x;
    const int b = idx / width, j = idx - b * width;
    float* p = g_XZ + (size_t)b * FEAT + off + j;
    *p = fmaf(*p, g_dss[0], g_dss[1]);
}

// Final projection: out = H @ cw2^T + cb2. grid = NB, block = 128
__global__ void k_out(const float* __restrict__ cw2, const float* __restrict__ cb2,
                      float* __restrict__ out) {
    const int b = blockIdx.x;
    const float* h = g_H + (size_t)b * HID;
    float a0 = 0.f, a1 = 0.f;
    for (int j = threadIdx.x; j < HID; j += 128) {
        const float hv = h[j];
        a0 = fmaf(hv, cw2[j], a0);
        a1 = fmaf(hv, cw2[HID + j], a1);
    }
    a0 = wsum(a0);
    a1 = wsum(a1);
    __shared__ float sh[8];
    const int w = threadIdx.x >> 5, lane = threadIdx.x & 31;
    if (lane == 0) { sh[w] = a0; sh[4 + w] = a1; }
    __syncthreads();
    if (threadIdx.x == 0) {
        out[b * 2 + 0] = sh[0] + sh[1] + sh[2] + sh[3] + cb2[0];
        out[b * 2 + 1] = sh[4] + sh[5] + sh[6] + sh[7] + cb2[1];
    }
}

// ----------------------------------------------------------------------------
// Host orchestration (graph-capturable: kernel launches only)
// ----------------------------------------------------------------------------
extern "C" void kernel_launch(void* const* d_in, const int* in_sizes, int n_in,
                              void* d_out, int out_size) {
    const float* X_in  = (const float*)d_in[0];
    const float* Z_in  = (const float*)d_in[1];
    const float* aw1   = (const float*)d_in[2];
    const float* ab1   = (const float*)d_in[3];
    const float* aw2   = (const float*)d_in[4];
    const float* ab2   = (const float*)d_in[5];
    const float* nw    = (const float*)d_in[6];
    const float* nb    = (const float*)d_in[7];
    const float* ew    = (const float*)d_in[8];
    const float* eb    = (const float*)d_in[9];
    const float* gn_g  = (const float*)d_in[10];
    const float* gn_b  = (const float*)d_in[11];
    const float* ge_g  = (const float*)d_in[12];
    const float* ge_b  = (const float*)d_in[13];
    const float* dn_w  = (const float*)d_in[14];
    const float* dn_b  = (const float*)d_in[15];
    const float* dn_g  = (const float*)d_in[16];
    const float* dn_be = (const float*)d_in[17];
    const float* de_w  = (const float*)d_in[18];
    const float* de_b  = (const float*)d_in[19];
    const float* de_g  = (const float*)d_in[20];
    const float* de_be = (const float*)d_in[21];
    const float* cw1   = (const float*)d_in[22];
    const float* cb1   = (const float*)d_in[23];
    const float* cw2   = (const float*)d_in[24];
    const float* cb2   = (const float*)d_in[25];
    float* out = (float*)d_out;

    float *pZ, *pAtt, *pVt, *pS, *pT, *pZ1, *pX, *pXZ, *pH;
    cudaGetSymbolAddress((void**)&pZ,  g_Z);
    cudaGetSymbolAddress((void**)&pAtt, g_att);
    cudaGetSymbolAddress((void**)&pVt, g_Vt);
    cudaGetSymbolAddress((void**)&pS,  g_S);
    cudaGetSymbolAddress((void**)&pT,  g_T);
    cudaGetSymbolAddress((void**)&pZ1, g_Z1);
    cudaGetSymbolAddress((void**)&pX,  g_X);
    cudaGetSymbolAddress((void**)&pXZ, g_XZ);
    cudaGetSymbolAddress((void**)&pH,  g_H);

    const size_t nZ = (size_t)NB * RR;
    const size_t nX = (size_t)NB * R * 3;
    k_copy<<<(unsigned)((nX + 255) / 256), 256>>>(X_in, pX, nX);
    k_copy<<<(unsigned)((nZ + 255) / 256), 256>>>(Z_in, pZ, nZ);

    auto down_node = [&](int l) {
        k_down_node<<<928, 128>>>(dn_w + 3 * l, dn_b + l, l * R);
        k_dreduce<<<1, 1024>>>(928, 1.f / (float)(NB * R), dn_g + l, dn_be + l);
        k_dapply<<<464, 256>>>(l * R, R);
    };
    auto down_edge = [&](int l) {
        k_down_edge<<<29696, 128>>>(de_w + 78 * l, de_b + l, 580 + l * 348);
        k_dreduce<<<1, 1024>>>(29696, 1.f / (float)(NB * R * 3), de_g + l, de_be + l);
        k_dapply<<<1392, 256>>>(580 + l * 348, 348);
    };

    down_node(0);
    down_edge(0);

    for (int i = 0; i < LAYERS; i++) {
        k_att<<<NB, 128>>>(aw1 + 9 * i, ab1 + 3 * i);
        // Vt[b] = Z[b] @ aw2^T + ab2  (NT, shared weight)
        k_gemm<128, 128, 8, 8, true><<<dim3(1, 1, NB), 256>>>(
            pZ, aw2 + (size_t)i * RR, ab2 + i * R, pVt,
            R, R, R, R, R, R, (size_t)RR, 0, (size_t)RR, 0);
        // S[b] = att[b] @ Vt[b]^T (NT, batched)
        k_gemm<128, 128, 8, 8, true><<<dim3(1, 1, NB), 256>>>(
            pAtt, pVt, nullptr, pS,
            R, R, R, R, R, R, (size_t)RR, (size_t)RR, (size_t)RR, 0);
        // T[b] = S[b]^T @ Z[b] (TN, batched)
        k_gemm<128, 128, 8, 8, false><<<dim3(1, 1, NB), 256>>>(
            pS, pZ, nullptr, pT,
            R, R, R, R, R, R, (size_t)RR, (size_t)RR, (size_t)RR, 0);
        // Z1[b] = T[b] @ ew^T + eb  (NT, shared weight)
        k_gemm<128, 128, 8, 8, true><<<dim3(1, 1, NB), 256>>>(
            pT, ew + (size_t)i * RR, eb + i * R, pZ1,
            R, R, R, R, R, R, (size_t)RR, 0, (size_t)RR, 0);
        // node path (uses old X + S), BN stats fused
        k_xpath<<<NB, 128>>>(nw + 9 * i, nb + 3 * i);
        k_reduce_chan<<<R, 256>>>(1.f / (float)(3 * NB), gn_g + i * R, gn_b + i * R);
        k_xapply<<<(NB * R * 3 + 255) / 256, 256>>>();
        // edge BN + residual
        k_zstats<<<NB, 128>>>();
        k_reduce_chan<<<R, 256>>>(1.f / (float)(NB * R), ge_g + i * R, ge_b + i * R);
        k_zapply<<<dim3(R, NB), 128>>>();
        down_edge(i + 1);
        down_node(i + 1);
    }

    // classifier: H = relu(XZ @ cw1^T + cb1)
    k_gemm<128, 64, 8, 4, true><<<dim3(HID / 64, NB / 128, 1), 256>>>(
        pXZ, cw1, cb1, pH,
        NB, HID, FEAT, FEAT, FEAT, HID, 0, 0, 0, 1);
    k_out<<<NB, 128>>>(cw2, cb2, out);
}

// round 3
// speedup vs baseline: 1.5984x; 1.5984x over previous
#include <cuda_runtime.h>
#include <cstddef>
#include <cstdint>

// ----------------------------------------------------------------------------
// Problem constants
// ----------------------------------------------------------------------------
#define NB 1024            // batch
#define R 116              // ROIs
#define RR (R * R)         // 13456
#define LAYERS 4
#define FEAT 2320          // R*4*(L+1)
#define HID 1024
#define MAXDB 32768
#define EPS 1e-5f

// ----------------------------------------------------------------------------
// Device scratch (static allocation only — no cudaMalloc allowed)
// ----------------------------------------------------------------------------
__device__ __align__(16) float g_Z  [(size_t)NB * RR];
__device__ __align__(16) float g_Zt [(size_t)NB * RR];
__device__ __align__(16) float g_att[(size_t)NB * RR];
__device__ __align__(16) float g_Vt [(size_t)NB * RR];
__device__ __align__(16) float g_S  [(size_t)NB * RR];   // S2 == reference A matrix [m][n]
__device__ __align__(16) float g_T  [(size_t)NB * RR];
__device__ __align__(16) float g_Z1 [(size_t)NB * RR];
__device__ __align__(16) float g_X  [NB * R * 3];
__device__ __align__(16) float g_X1 [NB * R * 3];
__device__ __align__(16) float g_XZ [(size_t)NB * FEAT];
__device__ __align__(16) float g_H  [(size_t)NB * HID];
__device__ float g_ps[R * NB];
__device__ float g_pq[R * NB];
__device__ float g_scale[R];
__device__ float g_shift[R];
__device__ float g_dpart[2 * MAXDB];
__device__ float g_dss[2];

__device__ __forceinline__ float wsum(float v) {
#pragma unroll
    for (int o = 16; o; o >>= 1) v += __shfl_xor_sync(0xffffffffu, v, o);
    return v;
}

__device__ __forceinline__ float to_tf32(float x) {
    float y;
    asm("cvt.rna.tf32.f32 %0, %1;" : "=f"(y) : "f"(x));
    return y;
}

// mma.sync m16n8k8 tf32: d += a (16x8, row) * b (8x8, col)
__device__ __forceinline__ void mma8(float* d, const uint32_t* a, const uint32_t* b) {
    asm volatile(
        "mma.sync.aligned.m16n8k8.row.col.f32.tf32.tf32.f32 "
        "{%0,%1,%2,%3},{%4,%5,%6,%7},{%8,%9},{%0,%1,%2,%3};"
        : "+f"(d[0]), "+f"(d[1]), "+f"(d[2]), "+f"(d[3])
        : "r"(a[0]), "r"(a[1]), "r"(a[2]), "r"(a[3]), "r"(b[0]), "r"(b[1]));
}

// ----------------------------------------------------------------------------
// Batched tf32 NT GEMM (whole 116x116 matrices in smem, one block per batch).
// C[b][i][j] = sum_k A[b][i][k] * B[b*bstrideB][j][k] + bias[j]
// dostats: per-row sum/sumsq of C into g_ps/g_pq (deterministic order).
// Block = 256 threads = 8 warps (2 x 4); warp tile 64x32; mma m16n8k8.
// smem row stride 124 floats => conflict-free fragment loads.
// ----------------------------------------------------------------------------
#define BGEMM_SMEM_FLOATS 32896
#define BGEMM_SMEM_BYTES (BGEMM_SMEM_FLOATS * 4)

__global__ void __launch_bounds__(256, 1)
k_bgemm(const float* __restrict__ A, const float* __restrict__ Bm,
        const float* __restrict__ bias, float* __restrict__ C,
        int bstrideB, int dostats)
{
    extern __shared__ float sm[];
    float* sA = sm;                 // 128 x 124
    float* sB = sm + 15872;         // 128 x 124
    float* sbias = sm + 31744;      // 128
    float* pS = sm + 31872;         // 4 x 128
    float* pQ = sm + 32384;         // 4 x 128

    const int tid = threadIdx.x;
    const int b = blockIdx.x;
    const int wid = tid >> 5, lane = tid & 31;
    const int wm = wid >> 2, wn = wid & 3;
    const int g = lane >> 2, tig = lane & 3;

    if (tid < 128) sbias[tid] = (bias != nullptr && tid < R) ? bias[tid] : 0.f;
    for (int i = tid; i < 31744; i += 256) sm[i] = 0.f;
    __syncthreads();

    const float* Ab = A + (size_t)b * RR;
    const float* Bb = Bm + (size_t)b * (size_t)bstrideB;
    for (int idx = tid; idx < 116 * 29; idx += 256) {
        const int r = idx / 29;
        const int c = (idx - r * 29) << 2;
        const float4 va = *(const float4*)(Ab + r * R + c);
        const float4 vb = *(const float4*)(Bb + r * R + c);
        float* da = sA + r * 124 + c;
        da[0] = to_tf32(va.x); da[1] = to_tf32(va.y);
        da[2] = to_tf32(va.z); da[3] = to_tf32(va.w);
        float* db = sB + r * 124 + c;
        db[0] = to_tf32(vb.x); db[1] = to_tf32(vb.y);
        db[2] = to_tf32(vb.z); db[3] = to_tf32(vb.w);
    }
    __syncthreads();

    float acc[4][4][4];
#pragma unroll
    for (int mt = 0; mt < 4; mt++)
#pragma unroll
        for (int nt = 0; nt < 4; nt++)
#pragma unroll
            for (int i = 0; i < 4; i++) acc[mt][nt][i] = 0.f;

#pragma unroll
    for (int ks = 0; ks < 15; ks++) {
        const int k0 = ks * 8;
        uint32_t af[4][4], bf[4][2];
#pragma unroll
        for (int mt = 0; mt < 4; mt++) {
            const float* p0 = sA + (wm * 64 + mt * 16 + g) * 124 + k0 + tig;
            af[mt][0] = __float_as_uint(p0[0]);
            af[mt][1] = __float_as_uint(p0[8 * 124]);
            af[mt][2] = __float_as_uint(p0[4]);
            af[mt][3] = __float_as_uint(p0[8 * 124 + 4]);
        }
#pragma unroll
        for (int nt = 0; nt < 4; nt++) {
            const float* p0 = sB + (wn * 32 + nt * 8 + g) * 124 + k0 + tig;
            bf[nt][0] = __float_as_uint(p0[0]);
            bf[nt][1] = __float_as_uint(p0[4]);
        }
#pragma unroll
        for (int mt = 0; mt < 4; mt++)
#pragma unroll
            for (int nt = 0; nt < 4; nt++)
                mma8(acc[mt][nt], af[mt], bf[nt]);
    }

    float* Cb = C + (size_t)b * RR;
#pragma unroll
    for (int mt = 0; mt < 4; mt++) {
#pragma unroll
        for (int h = 0; h < 2; h++) {
            const int row = wm * 64 + mt * 16 + g + 8 * h;
            float s = 0.f, q = 0.f;
#pragma unroll
            for (int nt = 0; nt < 4; nt++) {
                const int col = wn * 32 + nt * 8 + 2 * tig;
                if (col < R) {
                    const float v0 = acc[mt][nt][2 * h] + sbias[col];
                    const float v1 = acc[mt][nt][2 * h + 1] + sbias[col + 1];
                    if (row < R)
                        *(float2*)(Cb + (size_t)row * R + col) = make_float2(v0, v1);
                    s += v0 + v1;
                    q += v0 * v0 + v1 * v1;
                }
            }
            if (dostats) {
                s += __shfl_xor_sync(0xffffffffu, s, 1);
                s += __shfl_xor_sync(0xffffffffu, s, 2);
                q += __shfl_xor_sync(0xffffffffu, q, 1);
                q += __shfl_xor_sync(0xffffffffu, q, 2);
                if (tig == 0) { pS[wn * 128 + row] = s; pQ[wn * 128 + row] = q; }
            }
        }
    }
    if (dostats) {
        __syncthreads();
        if (tid < R) {
            const float s = pS[tid] + pS[128 + tid] + pS[256 + tid] + pS[384 + tid];
            const float q = pQ[tid] + pQ[128 + tid] + pQ[256 + tid] + pQ[384 + tid];
            g_ps[tid * NB + b] = s;
            g_pq[tid * NB + b] = q;
        }
    }
}

// ----------------------------------------------------------------------------
// Classifier GEMM: H[r][c] = relu(sum_k XZ[r][k]*cw1[c][k] + cb1[c])
// Tile 128x64, BK=16 double-buffered, 8 warps (4 x 2), warp tile 32x32.
// FEAT = 2320 = 145 * 16, exact; HID/64=16, NB/128=8 -> grid 128 blocks.
// ----------------------------------------------------------------------------
__global__ void __launch_bounds__(256)
k_cls(const float* __restrict__ A, const float* __restrict__ Bm,
      const float* __restrict__ bias, float* __restrict__ C)
{
    __shared__ float sA[2][128 * 20];
    __shared__ float sB[2][64 * 20];
    __shared__ float sbc[64];
    const int tid = threadIdx.x;
    const int wid = tid >> 5, lane = tid & 31;
    const int wm = wid >> 1, wn = wid & 1;
    const int g = lane >> 2, tig = lane & 3;
    const int row0 = blockIdx.y * 128, col0 = blockIdx.x * 64;

    if (tid < 64) sbc[tid] = bias[col0 + tid];

    float4 pa0, pa1, pb;
    const int ar0 = tid >> 2, ac0 = (tid & 3) << 2;          // f4 id = tid
    const int ar1 = (tid + 256) >> 2, ac1 = ac0;             // f4 id = tid + 256
    const int br = tid >> 2, bc = (tid & 3) << 2;

    auto fetch = [&](int k0) {
        pa0 = *(const float4*)(A + (size_t)(row0 + ar0) * FEAT + k0 + ac0);
        pa1 = *(const float4*)(A + (size_t)(row0 + ar1) * FEAT + k0 + ac1);
        pb  = *(const float4*)(Bm + (size_t)(col0 + br) * FEAT + k0 + bc);
    };
    auto store = [&](int buf) {
        float* d0 = &sA[buf][ar0 * 20 + ac0];
        d0[0] = to_tf32(pa0.x); d0[1] = to_tf32(pa0.y);
        d0[2] = to_tf32(pa0.z); d0[3] = to_tf32(pa0.w);
        float* d1 = &sA[buf][ar1 * 20 + ac1];
        d1[0] = to_tf32(pa1.x); d1[1] = to_tf32(pa1.y);
        d1[2] = to_tf32(pa1.z); d1[3] = to_tf32(pa1.w);
        float* d2 = &sB[buf][br * 20 + bc];
        d2[0] = to_tf32(pb.x); d2[1] = to_tf32(pb.y);
        d2[2] = to_tf32(pb.z); d2[3] = to_tf32(pb.w);
    };

    float acc[2][4][4];
#pragma unroll
    for (int mt = 0; mt < 2; mt++)
#pragma unroll
        for (int nt = 0; nt < 4; nt++)
#pragma unroll
            for (int i = 0; i < 4; i++) acc[mt][nt][i] = 0.f;

    const int NS = FEAT / 16;   // 145
    fetch(0);
    store(0);
    __syncthreads();
    int buf = 0;
    for (int ks = 0; ks < NS; ks++) {
        if (ks + 1 < NS) fetch((ks + 1) * 16);
#pragma unroll
        for (int kk = 0; kk < 2; kk++) {
            const int k0 = kk * 8;
            uint32_t af[2][4], bf[4][2];
#pragma unroll
            for (int mt = 0; mt < 2; mt++) {
                const float* p0 = &sA[buf][(wm * 32 + mt * 16 + g) * 20 + k0 + tig];
                af[mt][0] = __float_as_uint(p0[0]);
                af[mt][1] = __float_as_uint(p0[8 * 20]);
                af[mt][2] = __float_as_uint(p0[4]);
                af[mt][3] = __float_as_uint(p0[8 * 20 + 4]);
            }
#pragma unroll
            for (int nt = 0; nt < 4; nt++) {
                const float* p0 = &sB[buf][(wn * 32 + nt * 8 + g) * 20 + k0 + tig];
                bf[nt][0] = __float_as_uint(p0[0]);
                bf[nt][1] = __float_as_uint(p0[4]);
            }
#pragma unroll
            for (int mt = 0; mt < 2; mt++)
#pragma unroll
                for (int nt = 0; nt < 4; nt++)
                    mma8(acc[mt][nt], af[mt], bf[nt]);
        }
        if (ks + 1 < NS) store(buf ^ 1);
        __syncthreads();
        buf ^= 1;
    }

#pragma unroll
    for (int mt = 0; mt < 2; mt++)
#pragma unroll
        for (int h = 0; h < 2; h++) {
            const int row = row0 + wm * 32 + mt * 16 + g + 8 * h;
#pragma unroll
            for (int nt = 0; nt < 4; nt++) {
                const int col = wn * 32 + nt * 8 + 2 * tig;
                const float v0 = fmaxf(acc[mt][nt][2 * h] + sbc[col], 0.f);
                const float v1 = fmaxf(acc[mt][nt][2 * h + 1] + sbc[col + 1], 0.f);
                *(float2*)(C + (size_t)row * HID + col0 + col) = make_float2(v0, v1);
            }
        }
}

// ----------------------------------------------------------------------------
// Generic copy
// ----------------------------------------------------------------------------
__global__ void k_copy(const float* __restrict__ src, float* __restrict__ dst, size_t n) {
    size_t i = (size_t)blockIdx.x * blockDim.x + threadIdx.x;
    if (i < n) dst[i] = src[i];
}

// Plain batched transpose: dst[b][c][n] = src[b][n][c]
__global__ void k_transpose(const float* __restrict__ src, float* __restrict__ dst) {
    __shared__ float t[32][33];
    const int b = blockIdx.z;
    const int c0 = blockIdx.x * 32, n0 = blockIdx.y * 32;
    const float* S = src + (size_t)b * RR;
    float* D = dst + (size_t)b * RR;
    const int tx = threadIdx.x, ty = threadIdx.y;
#pragma unroll
    for (int j = 0; j < 32; j += 8) {
        const int n = n0 + ty + j, c = c0 + tx;
        if (n < R && c < R) t[ty + j][tx] = S[n * R + c];
    }
    __syncthreads();
#pragma unroll
    for (int j = 0; j < 32; j += 8) {
        const int c = c0 + ty + j, n = n0 + tx;
        if (c < R && n < R) D[c * R + n] = t[tx][ty + j];
    }
}

// Fused: Z += relu(bn(Z1)); also emit Zt = Z^T for next layer.
__global__ void k_zapply_t() {
    __shared__ float t[32][33];
    const int b = blockIdx.z;
    const int c0 = blockIdx.x * 32, n0 = blockIdx.y * 32;
    const size_t base = (size_t)b * RR;
    const int tx = threadIdx.x, ty = threadIdx.y;
#pragma unroll
    for (int j = 0; j < 32; j += 8) {
        const int n = n0 + ty + j, c = c0 + tx;
        if (n < R && c < R) {
            const size_t o = base + (size_t)n * R + c;
            const float y = fmaf(g_Z1[o], g_scale[n], g_shift[n]);
            const float v = g_Z[o] + fmaxf(y, 0.f);
            g_Z[o] = v;
            t[ty + j][tx] = v;
        }
    }
    __syncthreads();
#pragma unroll
    for (int j = 0; j < 32; j += 8) {
        const int c = c0 + ty + j, n = n0 + tx;
        if (c < R && n < R) g_Zt[base + (size_t)c * R + n] = t[tx][ty + j];
    }
}

// ----------------------------------------------------------------------------
// Attention: K = aw1@X^T + ab1 (3xR), scores = K^T K, row softmax -> g_att
// ----------------------------------------------------------------------------
__global__ void k_att(const float* __restrict__ aw1, const float* __restrict__ ab1) {
    __shared__ float Ks[R][3];
    const int b = blockIdx.x;
    const int tid = threadIdx.x;
    const float* Xb = g_X + (size_t)b * (R * 3);
    if (tid < R) {
        const float x0 = Xb[tid * 3 + 0], x1 = Xb[tid * 3 + 1], x2 = Xb[tid * 3 + 2];
#pragma unroll
        for (int o = 0; o < 3; o++)
            Ks[tid][o] = fmaf(aw1[o * 3 + 0], x0,
                         fmaf(aw1[o * 3 + 1], x1,
                         fmaf(aw1[o * 3 + 2], x2, ab1[o])));
    }
    __syncthreads();
    const int w = tid >> 5, lane = tid & 31;
    for (int n = w; n < R; n += 4) {
        const float k0 = Ks[n][0], k1 = Ks[n][1], k2 = Ks[n][2];
        float s[4];
        float mx = -3.0e38f;
#pragma unroll
        for (int it = 0; it < 4; it++) {
            const int m = it * 32 + lane;
            float v = -3.0e38f;
            if (m < R) v = k0 * Ks[m][0] + k1 * Ks[m][1] + k2 * Ks[m][2];
            s[it] = v;
            mx = fmaxf(mx, v);
        }
#pragma unroll
        for (int o = 16; o; o >>= 1) mx = fmaxf(mx, __shfl_xor_sync(0xffffffffu, mx, o));
        float sum = 0.f, e[4];
#pragma unroll
        for (int it = 0; it < 4; it++) {
            const int m = it * 32 + lane;
            e[it] = (m < R) ? __expf(s[it] - mx) : 0.f;
            sum += e[it];
        }
        sum = wsum(sum);
        const float inv = 1.f / sum;
        float* arow = g_att + ((size_t)b * R + n) * R;
#pragma unroll
        for (int it = 0; it < 4; it++) {
            const int m = it * 32 + lane;
            if (m < R) arow[m] = e[it] * inv;
        }
    }
}

// ----------------------------------------------------------------------------
// X path: X1[n] = (sum_m S2[n,m]*X[m]) @ nw^T + nb; BN partials per (n,b).
// ----------------------------------------------------------------------------
__global__ void k_xpath(const float* __restrict__ nw, const float* __restrict__ nb_) {
    const int b = blockIdx.x;
    __shared__ float Xs[R * 3];
    const float* Xb = g_X + (size_t)b * (R * 3);
    for (int i = threadIdx.x; i < R * 3; i += 128) Xs[i] = Xb[i];
    __syncthreads();
    const int n = threadIdx.x;
    if (n >= R) return;
    float a0 = 0.f, a1 = 0.f, a2 = 0.f;
    const float* Sb = g_S + (size_t)b * RR + (size_t)n * R;   // row n of S2
    for (int m = 0; m < R; m++) {
        const float s = Sb[m];
        a0 = fmaf(s, Xs[m * 3 + 0], a0);
        a1 = fmaf(s, Xs[m * 3 + 1], a1);
        a2 = fmaf(s, Xs[m * 3 + 2], a2);
    }
    float ps = 0.f, pq = 0.f;
    float* dst = g_X1 + (size_t)b * (R * 3) + n * 3;
#pragma unroll
    for (int o = 0; o < 3; o++) {
        const float v = fmaf(nw[o * 3 + 0], a0,
                        fmaf(nw[o * 3 + 1], a1,
                        fmaf(nw[o * 3 + 2], a2, nb_[o])));
        dst[o] = v;
        ps += v;
        pq = fmaf(v, v, pq);
    }
    g_ps[n * NB + b] = ps;
    g_pq[n * NB + b] = pq;
}

// Channel reduce: grid = R, block = 256 -> g_scale/g_shift
__global__ void k_reduce_chan(float invcnt, const float* __restrict__ gp,
                              const float* __restrict__ bp) {
    const int n = blockIdx.x;
    float s = 0.f, q = 0.f;
    for (int b = threadIdx.x; b < NB; b += 256) {
        s += g_ps[n * NB + b];
        q += g_pq[n * NB + b];
    }
    __shared__ float shs[8], shq[8];
    s = wsum(s); q = wsum(q);
    const int w = threadIdx.x >> 5, lane = threadIdx.x & 31;
    if (lane == 0) { shs[w] = s; shq[w] = q; }
    __syncthreads();
    if (w == 0) {
        s = (lane < 8) ? shs[lane] : 0.f;
        q = (lane < 8) ? shq[lane] : 0.f;
        s = wsum(s); q = wsum(q);
        if (lane == 0) {
            const float mean = s * invcnt;
            const float var = q * invcnt - mean * mean;
            const float rstd = rsqrtf(var + EPS);
            const float sc = rstd * gp[n];
            g_scale[n] = sc;
            g_shift[n] = bp[n] - mean * sc;
        }
    }
}

// X <- relu(bn(X1)) + X.
__global__ void k_xapply() {
    const int idx = blockIdx.x * 256 + threadIdx.x;
    if (idx >= NB * R * 3) return;
    const int n = (idx / 3) % R;
    const float y = fmaf(g_X1[idx], g_scale[n], g_shift[n]);
    g_X[idx] += fmaxf(y, 0.f);
}

// ----------------------------------------------------------------------------
// down_node
// ----------------------------------------------------------------------------
__global__ void k_down_node(const float* __restrict__ w, const float* __restrict__ bp,
                            int off) {
    const int idx = blockIdx.x * 128 + threadIdx.x;
    const float* x = g_X + (size_t)idx * 3;
    const float f = fmaxf(fmaf(x[0], w[0], fmaf(x[1], w[1], fmaf(x[2], w[2], bp[0]))), 0.f);
    const int b = idx / R, r = idx - b * R;
    g_XZ[(size_t)b * FEAT + off + r] = f;
    float s = wsum(f);
    float q = wsum(f * f);
    __shared__ float sh[8];
    const int wr = threadIdx.x >> 5, lane = threadIdx.x & 31;
    if (lane == 0) { sh[wr] = s; sh[4 + wr] = q; }
    __syncthreads();
    if (threadIdx.x == 0) {
        g_dpart[blockIdx.x] = sh[0] + sh[1] + sh[2] + sh[3];
        g_dpart[MAXDB + blockIdx.x] = sh[4] + sh[5] + sh[6] + sh[7];
    }
}

// ----------------------------------------------------------------------------
// down_edge
// ----------------------------------------------------------------------------
__global__ void k_down_edge(const float* __restrict__ w, const float* __restrict__ bp,
                            int off) {
    const int rowid = blockIdx.x * 4 + (threadIdx.x >> 5);
    const int lane = threadIdx.x & 31;
    const float* z = g_Z + (size_t)rowid * R;
    float f0 = 0.f, f1 = 0.f, f2 = 0.f;
    for (int j = lane; j < 78; j += 32) f1 = fmaf(z[j], w[j], f1);
    for (int j = lane; j < 39; j += 32) f0 = fmaf(z[j], w[39 + j], f0);
    for (int j = lane; j < 77; j += 32) f2 = fmaf(z[39 + j], w[j], f2);
    f0 = wsum(f0); f1 = wsum(f1); f2 = wsum(f2);
    float s = 0.f, q = 0.f;
    if (lane == 0) {
        const float bb = bp[0];
        f0 = fmaxf(f0 + bb, 0.f);
        f1 = fmaxf(f1 + bb, 0.f);
        f2 = fmaxf(f2 + bb, 0.f);
        const int b = rowid / R, r = rowid - (rowid / R) * R;
        float* dst = g_XZ + (size_t)b * FEAT + off + r * 3;
        dst[0] = f0; dst[1] = f1; dst[2] = f2;
        s = f0 + f1 + f2;
        q = f0 * f0 + f1 * f1 + f2 * f2;
    }
    __shared__ float sh[8];
    const int wr = threadIdx.x >> 5;
    if (lane == 0) { sh[wr] = s; sh[4 + wr] = q; }
    __syncthreads();
    if (threadIdx.x == 0) {
        g_dpart[blockIdx.x] = sh[0] + sh[1] + sh[2] + sh[3];
        g_dpart[MAXDB + blockIdx.x] = sh[4] + sh[5] + sh[6] + sh[7];
    }
}

__global__ void k_dreduce(int nblk, float invcnt, const float* __restrict__ gp,
                          const float* __restrict__ bp) {
    float s = 0.f, q = 0.f;
    for (int i = threadIdx.x; i < nblk; i += 1024) {
        s += g_dpart[i];
        q += g_dpart[MAXDB + i];
    }
    __shared__ float shs[32], shq[32];
    s = wsum(s); q = wsum(q);
    const int w = threadIdx.x >> 5, lane = threadIdx.x & 31;
    if (lane == 0) { shs[w] = s; shq[w] = q; }
    __syncthreads();
    if (w == 0) {
        s = shs[lane];
        q = shq[lane];
        s = wsum(s); q = wsum(q);
        if (lane == 0) {
            const float mean = s * invcnt;
            const float var = q * invcnt - mean * mean;
            const float rstd = rsqrtf(var + EPS);
            const float sc = rstd * gp[0];
            g_dss[0] = sc;
            g_dss[1] = bp[0] - mean * sc;
        }
    }
}

__global__ void k_dapply(int off, int width) {
    const int idx = blockIdx.x * 256 + threadIdx.x;
    const int b = idx / width, j = idx - b * width;
    float* p = g_XZ + (size_t)b * FEAT + off + j;
    *p = fmaf(*p, g_dss[0], g_dss[1]);
}

__global__ void k_out(const float* __restrict__ cw2, const float* __restrict__ cb2,
                      float* __restrict__ out) {
    const int b = blockIdx.x;
    const float* h = g_H + (size_t)b * HID;
    float a0 = 0.f, a1 = 0.f;
    for (int j = threadIdx.x; j < HID; j += 128) {
        const float hv = h[j];
        a0 = fmaf(hv, cw2[j], a0);
        a1 = fmaf(hv, cw2[HID + j], a1);
    }
    a0 = wsum(a0);
    a1 = wsum(a1);
    __shared__ float sh[8];
    const int w = threadIdx.x >> 5, lane = threadIdx.x & 31;
    if (lane == 0) { sh[w] = a0; sh[4 + w] = a1; }
    __syncthreads();
    if (threadIdx.x == 0) {
        out[b * 2 + 0] = sh[0] + sh[1] + sh[2] + sh[3] + cb2[0];
        out[b * 2 + 1] = sh[4] + sh[5] + sh[6] + sh[7] + cb2[1];
    }
}

// ----------------------------------------------------------------------------
// Host orchestration (graph-capturable: kernel launches only)
// ----------------------------------------------------------------------------
extern "C" void kernel_launch(void* const* d_in, const int* in_sizes, int n_in,
                              void* d_out, int out_size) {
    const float* X_in  = (const float*)d_in[0];
    const float* Z_in  = (const float*)d_in[1];
    const float* aw1   = (const float*)d_in[2];
    const float* ab1   = (const float*)d_in[3];
    const float* aw2   = (const float*)d_in[4];
    const float* ab2   = (const float*)d_in[5];
    const float* nw    = (const float*)d_in[6];
    const float* nb    = (const float*)d_in[7];
    const float* ew    = (const float*)d_in[8];
    const float* eb    = (const float*)d_in[9];
    const float* gn_g  = (const float*)d_in[10];
    const float* gn_b  = (const float*)d_in[11];
    const float* ge_g  = (const float*)d_in[12];
    const float* ge_b  = (const float*)d_in[13];
    const float* dn_w  = (const float*)d_in[14];
    const float* dn_b  = (const float*)d_in[15];
    const float* dn_g  = (const float*)d_in[16];
    const float* dn_be = (const float*)d_in[17];
    const float* de_w  = (const float*)d_in[18];
    const float* de_b  = (const float*)d_in[19];
    const float* de_g  = (const float*)d_in[20];
    const float* de_be = (const float*)d_in[21];
    const float* cw1   = (const float*)d_in[22];
    const float* cb1   = (const float*)d_in[23];
    const float* cw2   = (const float*)d_in[24];
    const float* cb2   = (const float*)d_in[25];
    float* out = (float*)d_out;

    cudaFuncSetAttribute(k_bgemm, cudaFuncAttributeMaxDynamicSharedMemorySize,
                         BGEMM_SMEM_BYTES);

    float *pZ, *pZt, *pAtt, *pVt, *pS, *pT, *pZ1, *pX, *pXZ, *pH;
    cudaGetSymbolAddress((void**)&pZ,   g_Z);
    cudaGetSymbolAddress((void**)&pZt,  g_Zt);
    cudaGetSymbolAddress((void**)&pAtt, g_att);
    cudaGetSymbolAddress((void**)&pVt,  g_Vt);
    cudaGetSymbolAddress((void**)&pS,   g_S);
    cudaGetSymbolAddress((void**)&pT,   g_T);
    cudaGetSymbolAddress((void**)&pZ1,  g_Z1);
    cudaGetSymbolAddress((void**)&pX,   g_X);
    cudaGetSymbolAddress((void**)&pXZ,  g_XZ);
    cudaGetSymbolAddress((void**)&pH,   g_H);

    const size_t nZ = (size_t)NB * RR;
    const size_t nX = (size_t)NB * R * 3;
    k_copy<<<(unsigned)((nX + 255) / 256), 256>>>(X_in, pX, nX);
    k_copy<<<(unsigned)((nZ + 255) / 256), 256>>>(Z_in, pZ, nZ);
    k_transpose<<<dim3(4, 4, NB), dim3(32, 8)>>>(pZ, pZt);

    auto down_node = [&](int l) {
        k_down_node<<<928, 128>>>(dn_w + 3 * l, dn_b + l, l * R);
        k_dreduce<<<1, 1024>>>(928, 1.f / (float)(NB * R), dn_g + l, dn_be + l);
        k_dapply<<<464, 256>>>(l * R, R);
    };
    auto down_edge = [&](int l) {
        k_down_edge<<<29696, 128>>>(de_w + 78 * l, de_b + l, 580 + l * 348);
        k_dreduce<<<1, 1024>>>(29696, 1.f / (float)(NB * R * 3), de_g + l, de_be + l);
        k_dapply<<<1392, 256>>>(580 + l * 348, 348);
    };

    down_node(0);
    down_edge(0);

    for (int i = 0; i < LAYERS; i++) {
        k_att<<<NB, 128>>>(aw1 + 9 * i, ab1 + 3 * i);
        // Vt[m,k] = sum_c Z[m,c]*aw2[k,c] + ab2[k]
        k_bgemm<<<NB, 256, BGEMM_SMEM_BYTES>>>(pZ, aw2 + (size_t)i * RR,
                                               ab2 + i * R, pVt, 0, 0);
        // S2[m,n] = sum_k Vt[m,k]*att[n,k]   (== reference A matrix)
        k_bgemm<<<NB, 256, BGEMM_SMEM_BYTES>>>(pVt, pAtt, nullptr, pS, RR, 0);
        // T[i,c] = sum_j S2[i,j]*Zt[c,j]
        k_bgemm<<<NB, 256, BGEMM_SMEM_BYTES>>>(pS, pZt, nullptr, pT, RR, 0);
        // Z1[i,o] = sum_c T[i,c]*ew[o,c] + eb[o]  (+ fused edge-BN partials)
        k_bgemm<<<NB, 256, BGEMM_SMEM_BYTES>>>(pT, ew + (size_t)i * RR,
                                               eb + i * R, pZ1, 0, 1);
        // edge BN apply (+ residual + transpose for next layer)
        k_reduce_chan<<<R, 256>>>(1.f / (float)(NB * R), ge_g + i * R, ge_b + i * R);
        k_zapply_t<<<dim3(4, 4, NB), dim3(32, 8)>>>();
        // node path (uses old X + S2)
        k_xpath<<<NB, 128>>>(nw + 9 * i, nb + 3 * i);
        k_reduce_chan<<<R, 256>>>(1.f / (float)(3 * NB), gn_g + i * R, gn_b + i * R);
        k_xapply<<<(NB * R * 3 + 255) / 256, 256>>>();
        down_edge(i + 1);
        down_node(i + 1);
    }

    // classifier: H = relu(XZ @ cw1^T + cb1)
    k_cls<<<dim3(HID / 64, NB / 128), 256>>>(pXZ, cw1, cb1, pH);
    k_out<<<NB, 128>>>(cw2, cb2, out);
}

// round 4
// speedup vs baseline: 2.1498x; 1.3450x over previous
#include <cuda_runtime.h>
#include <cstddef>
#include <cstdint>

// ----------------------------------------------------------------------------
// Problem constants
// ----------------------------------------------------------------------------
#define NB 1024            // batch
#define R 116              // ROIs
#define RR (R * R)         // 13456
#define LAYERS 4
#define FEAT 2320          // R*4*(L+1)
#define HID 1024
#define MAXDB 32768
#define EPS 1e-5f

// ----------------------------------------------------------------------------
// Device scratch (static allocation only)
// ----------------------------------------------------------------------------
__device__ __align__(16) float g_Z  [(size_t)NB * RR];
__device__ __align__(16) float g_S  [(size_t)NB * RR];   // S2 == reference A matrix
__device__ __align__(16) float g_Z1 [(size_t)NB * RR];
__device__ __align__(16) float g_X  [NB * R * 3];
__device__ __align__(16) float g_X1 [NB * R * 3];
__device__ __align__(16) float g_XZ [(size_t)NB * FEAT];
__device__ __align__(16) float g_H  [(size_t)NB * HID];
__device__ float g_ps[R * NB];
__device__ float g_pq[R * NB];
__device__ float g_scale[R];
__device__ float g_shift[R];
__device__ float g_dpart[2 * MAXDB];
__device__ float g_dss[2];

__device__ __forceinline__ float wsum(float v) {
#pragma unroll
    for (int o = 16; o; o >>= 1) v += __shfl_xor_sync(0xffffffffu, v, o);
    return v;
}

__device__ __forceinline__ float to_tf32(float x) {
    float y;
    asm("cvt.rna.tf32.f32 %0, %1;" : "=f"(y) : "f"(x));
    return y;
}

// mma.sync m16n8k8 tf32: d += a (16x8, row) * b (8x8, col)
__device__ __forceinline__ void mma8(float* d, const uint32_t* a, const uint32_t* b) {
    asm volatile(
        "mma.sync.aligned.m16n8k8.row.col.f32.tf32.tf32.f32 "
        "{%0,%1,%2,%3},{%4,%5,%6,%7},{%8,%9},{%0,%1,%2,%3};"
        : "+f"(d[0]), "+f"(d[1]), "+f"(d[2]), "+f"(d[3])
        : "r"(a[0]), "r"(a[1]), "r"(a[2]), "r"(a[3]), "r"(b[0]), "r"(b[1]));
}

// Shared mainloop over whole 128x(120)x128 smem tiles, stride 124.
__device__ __forceinline__ void mm_loop(const float* __restrict__ sA,
                                        const float* __restrict__ sB,
                                        float (&acc)[4][4][4],
                                        int wm, int wn, int g, int tig) {
#pragma unroll
    for (int ks = 0; ks < 15; ks++) {
        const int k0 = ks * 8;
        uint32_t af[4][4], bf[4][2];
#pragma unroll
        for (int mt = 0; mt < 4; mt++) {
            const float* p0 = sA + (wm * 64 + mt * 16 + g) * 124 + k0 + tig;
            af[mt][0] = __float_as_uint(p0[0]);
            af[mt][1] = __float_as_uint(p0[8 * 124]);
            af[mt][2] = __float_as_uint(p0[4]);
            af[mt][3] = __float_as_uint(p0[8 * 124 + 4]);
        }
#pragma unroll
        for (int nt = 0; nt < 4; nt++) {
            const float* p0 = sB + (wn * 32 + nt * 8 + g) * 124 + k0 + tig;
            bf[nt][0] = __float_as_uint(p0[0]);
            bf[nt][1] = __float_as_uint(p0[4]);
        }
#pragma unroll
        for (int mt = 0; mt < 4; mt++)
#pragma unroll
            for (int nt = 0; nt < 4; nt++)
                mma8(acc[mt][nt], af[mt], bf[nt]);
    }
}

// ----------------------------------------------------------------------------
// Fused chained batched GEMM: one CTA per batch b.
//   compute1: Mid = A @ B1^T (+bias1), kept in SMEM (tf32).
//   compute2: C = Mid @ B2^T (+bias2); B2 is either the in-kernel attention
//             matrix (ATT2=true) or a loaded tile (ATT2=false).
// TRANSB1: B1 tile is transposed during SMEM store (B1[j][c] -> sB[c][j]).
// dostats: per-output-row sum/sumsq into g_ps/g_pq.
// SMEM layout (floats): sA[0,15872) sB[15872,31744) sb1[31744,128) sb2[31872,128)
//                       sKs/pS[32000,512) pQ[32512,512)   total 33024
// ----------------------------------------------------------------------------
#define G2_SMEM_FLOATS 33024
#define G2_SMEM_BYTES (G2_SMEM_FLOATS * 4)

template <bool TRANSB1, bool ATT2>
__global__ void __launch_bounds__(256, 1)
k_gemm2(const float* __restrict__ A,
        const float* __restrict__ B1, int bs1, const float* __restrict__ bias1,
        const float* __restrict__ B2, int bs2, const float* __restrict__ bias2,
        const float* __restrict__ aw1, const float* __restrict__ ab1,
        float* __restrict__ C, int dostats)
{
    extern __shared__ float sm[];
    float* sA  = sm;
    float* sB  = sm + 15872;
    float* sb1 = sm + 31744;
    float* sb2 = sm + 31872;
    float* sKs = sm + 32000;   // 348 floats, reused as pS in epilogue
    float* pS  = sm + 32000;
    float* pQ  = sm + 32512;

    const int tid = threadIdx.x;
    const int b = blockIdx.x;
    const int wid = tid >> 5, lane = tid & 31;
    const int wm = wid >> 2, wn = wid & 3;
    const int g = lane >> 2, tig = lane & 3;
    const float4 z4 = make_float4(0.f, 0.f, 0.f, 0.f);

    // ---- phase 0: biases, Ks, pad zeroing, tile loads ----
    if (tid < 128) {
        sb1[tid] = (bias1 != nullptr && tid < R) ? bias1[tid] : 0.f;
        sb2[tid] = (bias2 != nullptr && tid < R) ? bias2[tid] : 0.f;
    }
    if (ATT2 && tid < R) {
        const float* xp = g_X + (size_t)b * (R * 3) + tid * 3;
        const float x0 = xp[0], x1 = xp[1], x2 = xp[2];
#pragma unroll
        for (int o = 0; o < 3; o++)
            sKs[tid * 3 + o] = fmaf(aw1[o * 3 + 0], x0,
                                fmaf(aw1[o * 3 + 1], x1,
                                fmaf(aw1[o * 3 + 2], x2, ab1[o])));
    }
    // zero pad rows 116..127 (full 124 cols), both tiles
    for (int idx = tid; idx < 2 * 12 * 31; idx += 256) {
        const int t = idx >= 372;
        const int i2 = idx - t * 372;
        const int r = 116 + i2 / 31, c = (i2 - (i2 / 31) * 31) * 4;
        *(float4*)((t ? sB : sA) + r * 124 + c) = z4;
    }
    // zero pad cols 116..119 for rows 0..115, both tiles
    for (int idx = tid; idx < 232; idx += 256) {
        const int t = idx >= 116;
        const int r = idx - t * 116;
        *(float4*)((t ? sB : sA) + r * 124 + 116) = z4;
    }
    // main tile loads
    {
        const float* Ab = A + (size_t)b * RR;
        const float* B1b = B1 + (size_t)b * (size_t)bs1;
        for (int idx = tid; idx < 116 * 29; idx += 256) {
            const int r = idx / 29;
            const int c = (idx - r * 29) << 2;
            const float4 va = *(const float4*)(Ab + r * R + c);
            float* da = sA + r * 124 + c;
            da[0] = to_tf32(va.x); da[1] = to_tf32(va.y);
            da[2] = to_tf32(va.z); da[3] = to_tf32(va.w);
            const float4 vb = *(const float4*)(B1b + r * R + c);
            if (TRANSB1) {
                sB[(c + 0) * 124 + r] = to_tf32(vb.x);
                sB[(c + 1) * 124 + r] = to_tf32(vb.y);
                sB[(c + 2) * 124 + r] = to_tf32(vb.z);
                sB[(c + 3) * 124 + r] = to_tf32(vb.w);
            } else {
                float* db = sB + r * 124 + c;
                db[0] = to_tf32(vb.x); db[1] = to_tf32(vb.y);
                db[2] = to_tf32(vb.z); db[3] = to_tf32(vb.w);
            }
        }
    }
    __syncthreads();

    float acc[4][4][4];
#pragma unroll
    for (int mt = 0; mt < 4; mt++)
#pragma unroll
        for (int nt = 0; nt < 4; nt++)
#pragma unroll
            for (int i = 0; i < 4; i++) acc[mt][nt][i] = 0.f;

    // ---- compute 1 ----
    mm_loop(sA, sB, acc, wm, wn, g, tig);
    __syncthreads();

    // ---- intermediate: write Mid (+bias1, tf32) into sA; build new sB ----
#pragma unroll
    for (int mt = 0; mt < 4; mt++)
#pragma unroll
        for (int h = 0; h < 2; h++) {
            const int row = wm * 64 + mt * 16 + g + 8 * h;
#pragma unroll
            for (int nt = 0; nt < 4; nt++) {
                const int col = wn * 32 + nt * 8 + 2 * tig;
                if (col < 120) {
                    sA[row * 124 + col]     = to_tf32(acc[mt][nt][2 * h] + sb1[col]);
                    sA[row * 124 + col + 1] = to_tf32(acc[mt][nt][2 * h + 1] + sb1[col + 1]);
                }
            }
        }
#pragma unroll
    for (int mt = 0; mt < 4; mt++)
#pragma unroll
        for (int nt = 0; nt < 4; nt++)
#pragma unroll
            for (int i = 0; i < 4; i++) acc[mt][nt][i] = 0.f;

    if (ATT2) {
        // attention rows: one warp per row n, softmax over 116 cols -> sB (tf32)
        for (int n = wid; n < R; n += 8) {
            const float k0 = sKs[n * 3], k1 = sKs[n * 3 + 1], k2 = sKs[n * 3 + 2];
            float s[4];
            float mx = -3.0e38f;
#pragma unroll
            for (int it = 0; it < 4; it++) {
                const int m = it * 32 + lane;
                float v = -3.0e38f;
                if (m < R)
                    v = k0 * sKs[m * 3] + k1 * sKs[m * 3 + 1] + k2 * sKs[m * 3 + 2];
                s[it] = v;
                mx = fmaxf(mx, v);
            }
#pragma unroll
            for (int o = 16; o; o >>= 1)
                mx = fmaxf(mx, __shfl_xor_sync(0xffffffffu, mx, o));
            float sum = 0.f, e[4];
#pragma unroll
            for (int it = 0; it < 4; it++) {
                const int m = it * 32 + lane;
                e[it] = (m < R) ? __expf(s[it] - mx) : 0.f;
                sum += e[it];
            }
            sum = wsum(sum);
            const float inv = 1.f / sum;
#pragma unroll
            for (int it = 0; it < 4; it++) {
                const int m = it * 32 + lane;
                if (m < R) sB[n * 124 + m] = to_tf32(e[it] * inv);
            }
        }
    } else {
        const float* B2b = B2 + (size_t)b * (size_t)bs2;
        for (int idx = tid; idx < 116 * 29; idx += 256) {
            const int r = idx / 29;
            const int c = (idx - r * 29) << 2;
            const float4 vb = *(const float4*)(B2b + r * R + c);
            float* db = sB + r * 124 + c;
            db[0] = to_tf32(vb.x); db[1] = to_tf32(vb.y);
            db[2] = to_tf32(vb.z); db[3] = to_tf32(vb.w);
        }
    }
    __syncthreads();

    // ---- compute 2 ----
    mm_loop(sA, sB, acc, wm, wn, g, tig);

    // ---- epilogue ----
    float* Cb = C + (size_t)b * RR;
#pragma unroll
    for (int mt = 0; mt < 4; mt++) {
#pragma unroll
        for (int h = 0; h < 2; h++) {
            const int row = wm * 64 + mt * 16 + g + 8 * h;
            float s = 0.f, q = 0.f;
#pragma unroll
            for (int nt = 0; nt < 4; nt++) {
                const int col = wn * 32 + nt * 8 + 2 * tig;
                if (col < R) {
                    const float v0 = acc[mt][nt][2 * h] + sb2[col];
                    const float v1 = acc[mt][nt][2 * h + 1] + sb2[col + 1];
                    if (row < R)
                        *(float2*)(Cb + (size_t)row * R + col) = make_float2(v0, v1);
                    s += v0 + v1;
                    q += v0 * v0 + v1 * v1;
                }
            }
            if (dostats) {
                s += __shfl_xor_sync(0xffffffffu, s, 1);
                s += __shfl_xor_sync(0xffffffffu, s, 2);
                q += __shfl_xor_sync(0xffffffffu, q, 1);
                q += __shfl_xor_sync(0xffffffffu, q, 2);
                if (tig == 0) { pS[wn * 128 + row] = s; pQ[wn * 128 + row] = q; }
            }
        }
    }
    if (dostats) {
        __syncthreads();
        if (tid < R) {
            const float s = pS[tid] + pS[128 + tid] + pS[256 + tid] + pS[384 + tid];
            const float q = pQ[tid] + pQ[128 + tid] + pQ[256 + tid] + pQ[384 + tid];
            g_ps[tid * NB + b] = s;
            g_pq[tid * NB + b] = q;
        }
    }
}

// ----------------------------------------------------------------------------
// Classifier GEMM (unchanged from R3, tile 128x64, BK=16 double-buffered)
// ----------------------------------------------------------------------------
__global__ void __launch_bounds__(256)
k_cls(const float* __restrict__ A, const float* __restrict__ Bm,
      const float* __restrict__ bias, float* __restrict__ C)
{
    __shared__ float sA[2][128 * 20];
    __shared__ float sB[2][64 * 20];
    __shared__ float sbc[64];
    const int tid = threadIdx.x;
    const int wid = tid >> 5, lane = tid & 31;
    const int wm = wid >> 1, wn = wid & 1;
    const int g = lane >> 2, tig = lane & 3;
    const int row0 = blockIdx.y * 128, col0 = blockIdx.x * 64;

    if (tid < 64) sbc[tid] = bias[col0 + tid];

    float4 pa0, pa1, pb;
    const int ar0 = tid >> 2, ac0 = (tid & 3) << 2;
    const int ar1 = (tid + 256) >> 2, ac1 = ac0;
    const int br = tid >> 2, bc = (tid & 3) << 2;

    auto fetch = [&](int k0) {
        pa0 = *(const float4*)(A + (size_t)(row0 + ar0) * FEAT + k0 + ac0);
        pa1 = *(const float4*)(A + (size_t)(row0 + ar1) * FEAT + k0 + ac1);
        pb  = *(const float4*)(Bm + (size_t)(col0 + br) * FEAT + k0 + bc);
    };
    auto store = [&](int buf) {
        float* d0 = &sA[buf][ar0 * 20 + ac0];
        d0[0] = to_tf32(pa0.x); d0[1] = to_tf32(pa0.y);
        d0[2] = to_tf32(pa0.z); d0[3] = to_tf32(pa0.w);
        float* d1 = &sA[buf][ar1 * 20 + ac1];
        d1[0] = to_tf32(pa1.x); d1[1] = to_tf32(pa1.y);
        d1[2] = to_tf32(pa1.z); d1[3] = to_tf32(pa1.w);
        float* d2 = &sB[buf][br * 20 + bc];
        d2[0] = to_tf32(pb.x); d2[1] = to_tf32(pb.y);
        d2[2] = to_tf32(pb.z); d2[3] = to_tf32(pb.w);
    };

    float acc[2][4][4];
#pragma unroll
    for (int mt = 0; mt < 2; mt++)
#pragma unroll
        for (int nt = 0; nt < 4; nt++)
#pragma unroll
            for (int i = 0; i < 4; i++) acc[mt][nt][i] = 0.f;

    const int NS = FEAT / 16;
    fetch(0);
    store(0);
    __syncthreads();
    int buf = 0;
    for (int ks = 0; ks < NS; ks++) {
        if (ks + 1 < NS) fetch((ks + 1) * 16);
#pragma unroll
        for (int kk = 0; kk < 2; kk++) {
            const int k0 = kk * 8;
            uint32_t af[2][4], bf[4][2];
#pragma unroll
            for (int mt = 0; mt < 2; mt++) {
                const float* p0 = &sA[buf][(wm * 32 + mt * 16 + g) * 20 + k0 + tig];
                af[mt][0] = __float_as_uint(p0[0]);
                af[mt][1] = __float_as_uint(p0[8 * 20]);
                af[mt][2] = __float_as_uint(p0[4]);
                af[mt][3] = __float_as_uint(p0[8 * 20 + 4]);
            }
#pragma unroll
            for (int nt = 0; nt < 4; nt++) {
                const float* p0 = &sB[buf][(wn * 32 + nt * 8 + g) * 20 + k0 + tig];
                bf[nt][0] = __float_as_uint(p0[0]);
                bf[nt][1] = __float_as_uint(p0[4]);
            }
#pragma unroll
            for (int mt = 0; mt < 2; mt++)
#pragma unroll
                for (int nt = 0; nt < 4; nt++)
                    mma8(acc[mt][nt], af[mt], bf[nt]);
        }
        if (ks + 1 < NS) store(buf ^ 1);
        __syncthreads();
        buf ^= 1;
    }

#pragma unroll
    for (int mt = 0; mt < 2; mt++)
#pragma unroll
        for (int h = 0; h < 2; h++) {
            const int row = row0 + wm * 32 + mt * 16 + g + 8 * h;
#pragma unroll
            for (int nt = 0; nt < 4; nt++) {
                const int col = wn * 32 + nt * 8 + 2 * tig;
                const float v0 = fmaxf(acc[mt][nt][2 * h] + sbc[col], 0.f);
                const float v1 = fmaxf(acc[mt][nt][2 * h + 1] + sbc[col + 1], 0.f);
                *(float2*)(C + (size_t)row * HID + col0 + col) = make_float2(v0, v1);
            }
        }
}

// ----------------------------------------------------------------------------
// Generic copy
// ----------------------------------------------------------------------------
__global__ void k_copy(const float* __restrict__ src, float* __restrict__ dst, size_t n) {
    size_t i = (size_t)blockIdx.x * blockDim.x + threadIdx.x;
    if (i < n) dst[i] = src[i];
}

// ----------------------------------------------------------------------------
// Fused: (optional) Z += relu(bn(Z1)), then down-edge conv windows + partials.
// Warp per (b,n) row. grid = NB*R/4 = 29696, block = 128.
// ----------------------------------------------------------------------------
__global__ void k_zapply_de(const float* __restrict__ w78, const float* __restrict__ bp,
                            int off, int apply) {
    __shared__ float sW[78];
    __shared__ float sh[8];
    if (threadIdx.x < 78) sW[threadIdx.x] = w78[threadIdx.x];
    __syncthreads();
    const int wrp = threadIdx.x >> 5, lane = threadIdx.x & 31;
    const int rowid = blockIdx.x * 4 + wrp;
    const int b = rowid / R, n = rowid - b * R;

    float4 v = make_float4(0.f, 0.f, 0.f, 0.f);
    float* zrow = g_Z + (size_t)rowid * R;
    if (lane < 29) {
        v = *(float4*)(zrow + 4 * lane);
        if (apply) {
            const float4 u = *(const float4*)(g_Z1 + (size_t)rowid * R + 4 * lane);
            const float sc = g_scale[n], sf = g_shift[n];
            v.x += fmaxf(fmaf(u.x, sc, sf), 0.f);
            v.y += fmaxf(fmaf(u.y, sc, sf), 0.f);
            v.z += fmaxf(fmaf(u.z, sc, sf), 0.f);
            v.w += fmaxf(fmaf(u.w, sc, sf), 0.f);
            *(float4*)(zrow + 4 * lane) = v;
        }
    }
    float f0 = 0.f, f1 = 0.f, f2 = 0.f;
    const float vv[4] = {v.x, v.y, v.z, v.w};
#pragma unroll
    for (int d = 0; d < 4; d++) {
        const int e = 4 * lane + d;
        if (e < 78) f1 = fmaf(vv[d], sW[e], f1);
        if (e < 39) f0 = fmaf(vv[d], sW[39 + e], f0);
        if (e >= 39 && e < 116) f2 = fmaf(vv[d], sW[e - 39], f2);
    }
    f0 = wsum(f0); f1 = wsum(f1); f2 = wsum(f2);
    float s = 0.f, q = 0.f;
    if (lane == 0) {
        const float bb = bp[0];
        f0 = fmaxf(f0 + bb, 0.f);
        f1 = fmaxf(f1 + bb, 0.f);
        f2 = fmaxf(f2 + bb, 0.f);
        float* dst = g_XZ + (size_t)b * FEAT + off + n * 3;
        dst[0] = f0; dst[1] = f1; dst[2] = f2;
        s = f0 + f1 + f2;
        q = f0 * f0 + f1 * f1 + f2 * f2;
        sh[wrp] = s; sh[4 + wrp] = q;
    }
    __syncthreads();
    if (threadIdx.x == 0) {
        g_dpart[blockIdx.x] = sh[0] + sh[1] + sh[2] + sh[3];
        g_dpart[MAXDB + blockIdx.x] = sh[4] + sh[5] + sh[6] + sh[7];
    }
}

// ----------------------------------------------------------------------------
// Fused: (optional) X += relu(bn(X1)), then down-node feature + partials.
// Thread per (b,r). grid = 928, block = 128.
// ----------------------------------------------------------------------------
__global__ void k_xapply_dn(const float* __restrict__ w3, const float* __restrict__ bp,
                            int off, int apply) {
    const int idx = blockIdx.x * 128 + threadIdx.x;
    float* xp = g_X + (size_t)idx * 3;
    float x0 = xp[0], x1 = xp[1], x2 = xp[2];
    if (apply) {
        const int n = idx % R;
        const float sc = g_scale[n], sf = g_shift[n];
        const float* up = g_X1 + (size_t)idx * 3;
        x0 += fmaxf(fmaf(up[0], sc, sf), 0.f);
        x1 += fmaxf(fmaf(up[1], sc, sf), 0.f);
        x2 += fmaxf(fmaf(up[2], sc, sf), 0.f);
        xp[0] = x0; xp[1] = x1; xp[2] = x2;
    }
    const float f = fmaxf(fmaf(x0, w3[0], fmaf(x1, w3[1], fmaf(x2, w3[2], bp[0]))), 0.f);
    const int b = idx / R, r = idx - b * R;
    g_XZ[(size_t)b * FEAT + off + r] = f;
    const float s = wsum(f);
    const float q = wsum(f * f);
    __shared__ float sh[8];
    const int wr = threadIdx.x >> 5, lane = threadIdx.x & 31;
    if (lane == 0) { sh[wr] = s; sh[4 + wr] = q; }
    __syncthreads();
    if (threadIdx.x == 0) {
        g_dpart[blockIdx.x] = sh[0] + sh[1] + sh[2] + sh[3];
        g_dpart[MAXDB + blockIdx.x] = sh[4] + sh[5] + sh[6] + sh[7];
    }
}

// ----------------------------------------------------------------------------
// X path: X1[n] = (sum_m S2[n,m]*X[m]) @ nw^T + nb; BN partials per (n,b).
// ----------------------------------------------------------------------------
__global__ void k_xpath(const float* __restrict__ nw, const float* __restrict__ nb_) {
    const int b = blockIdx.x;
    __shared__ float Xs[R * 3];
    const float* Xb = g_X + (size_t)b * (R * 3);
    for (int i = threadIdx.x; i < R * 3; i += 128) Xs[i] = Xb[i];
    __syncthreads();
    const int n = threadIdx.x;
    if (n >= R) return;
    float a0 = 0.f, a1 = 0.f, a2 = 0.f;
    const float* Sb = g_S + (size_t)b * RR + (size_t)n * R;
    for (int m = 0; m < R; m++) {
        const float s = Sb[m];
        a0 = fmaf(s, Xs[m * 3 + 0], a0);
        a1 = fmaf(s, Xs[m * 3 + 1], a1);
        a2 = fmaf(s, Xs[m * 3 + 2], a2);
    }
    float ps = 0.f, pq = 0.f;
    float* dst = g_X1 + (size_t)b * (R * 3) + n * 3;
#pragma unroll
    for (int o = 0; o < 3; o++) {
        const float v = fmaf(nw[o * 3 + 0], a0,
                        fmaf(nw[o * 3 + 1], a1,
                        fmaf(nw[o * 3 + 2], a2, nb_[o])));
        dst[o] = v;
        ps += v;
        pq = fmaf(v, v, pq);
    }
    g_ps[n * NB + b] = ps;
    g_pq[n * NB + b] = pq;
}

// Channel reduce: grid = R, block = 256 -> g_scale/g_shift
__global__ void k_reduce_chan(float invcnt, const float* __restrict__ gp,
                              const float* __restrict__ bp) {
    const int n = blockIdx.x;
    float s = 0.f, q = 0.f;
    for (int b = threadIdx.x; b < NB; b += 256) {
        s += g_ps[n * NB + b];
        q += g_pq[n * NB + b];
    }
    __shared__ float shs[8], shq[8];
    s = wsum(s); q = wsum(q);
    const int w = threadIdx.x >> 5, lane = threadIdx.x & 31;
    if (lane == 0) { shs[w] = s; shq[w] = q; }
    __syncthreads();
    if (w == 0) {
        s = (lane < 8) ? shs[lane] : 0.f;
        q = (lane < 8) ? shq[lane] : 0.f;
        s = wsum(s); q = wsum(q);
        if (lane == 0) {
            const float mean = s * invcnt;
            const float var = q * invcnt - mean * mean;
            const float rstd = rsqrtf(var + EPS);
            const float sc = rstd * gp[n];
            g_scale[n] = sc;
            g_shift[n] = bp[n] - mean * sc;
        }
    }
}

__global__ void k_dreduce(int nblk, float invcnt, const float* __restrict__ gp,
                          const float* __restrict__ bp) {
    float s = 0.f, q = 0.f;
    for (int i = threadIdx.x; i < nblk; i += 1024) {
        s += g_dpart[i];
        q += g_dpart[MAXDB + i];
    }
    __shared__ float shs[32], shq[32];
    s = wsum(s); q = wsum(q);
    const int w = threadIdx.x >> 5, lane = threadIdx.x & 31;
    if (lane == 0) { shs[w] = s; shq[w] = q; }
    __syncthreads();
    if (w == 0) {
        s = shs[lane];
        q = shq[lane];
        s = wsum(s); q = wsum(q);
        if (lane == 0) {
            const float mean = s * invcnt;
            const float var = q * invcnt - mean * mean;
            const float rstd = rsqrtf(var + EPS);
            const float sc = rstd * gp[0];
            g_dss[0] = sc;
            g_dss[1] = bp[0] - mean * sc;
        }
    }
}

__global__ void k_dapply(int off, int width) {
    const int idx = blockIdx.x * 256 + threadIdx.x;
    const int b = idx / width, j = idx - b * width;
    float* p = g_XZ + (size_t)b * FEAT + off + j;
    *p = fmaf(*p, g_dss[0], g_dss[1]);
}

__global__ void k_out(const float* __restrict__ cw2, const float* __restrict__ cb2,
                      float* __restrict__ out) {
    const int b = blockIdx.x;
    const float* h = g_H + (size_t)b * HID;
    float a0 = 0.f, a1 = 0.f;
    for (int j = threadIdx.x; j < HID; j += 128) {
        const float hv = h[j];
        a0 = fmaf(hv, cw2[j], a0);
        a1 = fmaf(hv, cw2[HID + j], a1);
    }
    a0 = wsum(a0);
    a1 = wsum(a1);
    __shared__ float sh[8];
    const int w = threadIdx.x >> 5, lane = threadIdx.x & 31;
    if (lane == 0) { sh[w] = a0; sh[4 + w] = a1; }
    __syncthreads();
    if (threadIdx.x == 0) {
        out[b * 2 + 0] = sh[0] + sh[1] + sh[2] + sh[3] + cb2[0];
        out[b * 2 + 1] = sh[4] + sh[5] + sh[6] + sh[7] + cb2[1];
    }
}

// ----------------------------------------------------------------------------
// Host orchestration (graph-capturable: kernel launches only)
// ----------------------------------------------------------------------------
extern "C" void kernel_launch(void* const* d_in, const int* in_sizes, int n_in,
                              void* d_out, int out_size) {
    const float* X_in  = (const float*)d_in[0];
    const float* Z_in  = (const float*)d_in[1];
    const float* aw1   = (const float*)d_in[2];
    const float* ab1   = (const float*)d_in[3];
    const float* aw2   = (const float*)d_in[4];
    const float* ab2   = (const float*)d_in[5];
    const float* nw    = (const float*)d_in[6];
    const float* nb    = (const float*)d_in[7];
    const float* ew    = (const float*)d_in[8];
    const float* eb    = (const float*)d_in[9];
    const float* gn_g  = (const float*)d_in[10];
    const float* gn_b  = (const float*)d_in[11];
    const float* ge_g  = (const float*)d_in[12];
    const float* ge_b  = (const float*)d_in[13];
    const float* dn_w  = (const float*)d_in[14];
    const float* dn_b  = (const float*)d_in[15];
    const float* dn_g  = (const float*)d_in[16];
    const float* dn_be = (const float*)d_in[17];
    const float* de_w  = (const float*)d_in[18];
    const float* de_b  = (const float*)d_in[19];
    const float* de_g  = (const float*)d_in[20];
    const float* de_be = (const float*)d_in[21];
    const float* cw1   = (const float*)d_in[22];
    const float* cb1   = (const float*)d_in[23];
    const float* cw2   = (const float*)d_in[24];
    const float* cb2   = (const float*)d_in[25];
    float* out = (float*)d_out;

    cudaFuncSetAttribute(k_gemm2<false, true>,
                         cudaFuncAttributeMaxDynamicSharedMemorySize, G2_SMEM_BYTES);
    cudaFuncSetAttribute(k_gemm2<true, false>,
                         cudaFuncAttributeMaxDynamicSharedMemorySize, G2_SMEM_BYTES);

    float *pZ, *pS, *pZ1, *pX, *pXZ, *pH;
    cudaGetSymbolAddress((void**)&pZ,  g_Z);
    cudaGetSymbolAddress((void**)&pS,  g_S);
    cudaGetSymbolAddress((void**)&pZ1, g_Z1);
    cudaGetSymbolAddress((void**)&pX,  g_X);
    cudaGetSymbolAddress((void**)&pXZ, g_XZ);
    cudaGetSymbolAddress((void**)&pH,  g_H);

    const size_t nZ = (size_t)NB * RR;
    const size_t nX = (size_t)NB * R * 3;
    k_copy<<<(unsigned)((nX + 255) / 256), 256>>>(X_in, pX, nX);
    k_copy<<<(unsigned)((nZ + 255) / 256), 256>>>(Z_in, pZ, nZ);

    auto down_node = [&](int l, int apply) {
        k_xapply_dn<<<928, 128>>>(dn_w + 3 * l, dn_b + l, l * R, apply);
        k_dreduce<<<1, 1024>>>(928, 1.f / (float)(NB * R), dn_g + l, dn_be + l);
        k_dapply<<<464, 256>>>(l * R, R);
    };
    auto down_edge = [&](int l, int apply) {
        k_zapply_de<<<29696, 128>>>(de_w + 78 * l, de_b + l, 580 + l * 348, apply);
        k_dreduce<<<1, 1024>>>(29696, 1.f / (float)(NB * R * 3), de_g + l, de_be + l);
        k_dapply<<<1392, 256>>>(580 + l * 348, 348);
    };

    down_node(0, 0);
    down_edge(0, 0);

    for (int i = 0; i < LAYERS; i++) {
        // Kernel A: Mid = Z@aw2^T + ab2; S2 = Mid @ att^T (att built in-kernel)
        k_gemm2<false, true><<<NB, 256, G2_SMEM_BYTES>>>(
            pZ, aw2 + (size_t)i * RR, 0, ab2 + i * R,
            nullptr, 0, nullptr, aw1 + 9 * i, ab1 + 3 * i, pS, 0);
        // Kernel B: Mid = S2 @ Z (Z transposed in smem); Z1 = Mid @ ew^T + eb, + stats
        k_gemm2<true, false><<<NB, 256, G2_SMEM_BYTES>>>(
            pS, pZ, RR, nullptr,
            ew + (size_t)i * RR, 0, eb + i * R, nullptr, nullptr, pZ1, 1);
        // node path first (needs OLD X + S2); stats buffers used sequentially:
        // edge stats (from kernel B) -> reduce -> zapply; then node stats.
        k_reduce_chan<<<R, 256>>>(1.f / (float)(NB * R), ge_g + i * R, ge_b + i * R);
        down_edge(i + 1, 1);
        k_xpath<<<NB, 128>>>(nw + 9 * i, nb + 3 * i);
        k_reduce_chan<<<R, 256>>>(1.f / (float)(3 * NB), gn_g + i * R, gn_b + i * R);
        down_node(i + 1, 1);
    }

    // classifier: H = relu(XZ @ cw1^T + cb1)
    k_cls<<<dim3(HID / 64, NB / 128), 256>>>(pXZ, cw1, cb1, pH);
    k_out<<<NB, 128>>>(cw2, cb2, out);
}

// round 5
// speedup vs baseline: 2.6300x; 1.2234x over previous
#include <cuda_runtime.h>
#include <cstddef>
#include <cstdint>

// ----------------------------------------------------------------------------
// Problem constants
// ----------------------------------------------------------------------------
#define NB 1024            // batch
#define R 116              // ROIs
#define RR (R * R)         // 13456
#define LAYERS 4
#define FEAT 2320          // R*4*(L+1)
#define HID 1024
#define EPS 1e-5f

#define STR 124            // smem tile row stride (floats)
#define REGF 15872         // floats per 128xSTR tile region
#define EDGET 148480       // 5 * 29696 edge partial slots
#define DPTOT 153120       // + 5 * 928 node slots

// ----------------------------------------------------------------------------
// Device scratch (static allocation only)
// ----------------------------------------------------------------------------
__device__ __align__(16) float g_Z  [(size_t)NB * RR];
__device__ __align__(16) float g_Z1 [(size_t)NB * RR];
__device__ __align__(16) float g_X  [NB * R * 3];
__device__ __align__(16) float g_X1 [NB * R * 3];
__device__ __align__(16) float g_XZ [(size_t)NB * FEAT];
__device__ __align__(16) float g_H  [(size_t)NB * HID];
__device__ float g_ps [R * NB];     // edge BN partials
__device__ float g_pq [R * NB];
__device__ float g_psN[R * NB];     // node BN partials
__device__ float g_pqN[R * NB];
__device__ float g_scale [R],  g_shift [R];   // edge BN affine
__device__ float g_scaleN[R],  g_shiftN[R];   // node BN affine
__device__ float g_dpS[DPTOT], g_dpQ[DPTOT];  // down-sample partials (per layer)
__device__ float g_dssArr[20];                // 10 segments x (scale, shift)

__device__ __forceinline__ float wsum(float v) {
#pragma unroll
    for (int o = 16; o; o >>= 1) v += __shfl_xor_sync(0xffffffffu, v, o);
    return v;
}

__device__ __forceinline__ float to_tf32(float x) {
    float y;
    asm("cvt.rna.tf32.f32 %0, %1;" : "=f"(y) : "f"(x));
    return y;
}

// mma.sync m16n8k8 tf32: d += a (16x8, row) * b (8x8, col)
__device__ __forceinline__ void mma8(float* d, const uint32_t* a, const uint32_t* b) {
    asm volatile(
        "mma.sync.aligned.m16n8k8.row.col.f32.tf32.tf32.f32 "
        "{%0,%1,%2,%3},{%4,%5,%6,%7},{%8,%9},{%0,%1,%2,%3};"
        : "+f"(d[0]), "+f"(d[1]), "+f"(d[2]), "+f"(d[3])
        : "r"(a[0]), "r"(a[1]), "r"(a[2]), "r"(a[3]), "r"(b[0]), "r"(b[1]));
}

// 128x128x120 NT GEMM over whole smem tiles (stride STR), conflict-free.
__device__ __forceinline__ void mm_loop(const float* __restrict__ sA,
                                        const float* __restrict__ sB,
                                        float (&acc)[4][4][4],
                                        int wm, int wn, int g, int tig) {
#pragma unroll
    for (int ks = 0; ks < 15; ks++) {
        const int k0 = ks * 8;
        uint32_t af[4][4], bf[4][2];
#pragma unroll
        for (int mt = 0; mt < 4; mt++) {
            const float* p0 = sA + (wm * 64 + mt * 16 + g) * STR + k0 + tig;
            af[mt][0] = __float_as_uint(p0[0]);
            af[mt][1] = __float_as_uint(p0[8 * STR]);
            af[mt][2] = __float_as_uint(p0[4]);
            af[mt][3] = __float_as_uint(p0[8 * STR + 4]);
        }
#pragma unroll
        for (int nt = 0; nt < 4; nt++) {
            const float* p0 = sB + (wn * 32 + nt * 8 + g) * STR + k0 + tig;
            bf[nt][0] = __float_as_uint(p0[0]);
            bf[nt][1] = __float_as_uint(p0[4]);
        }
#pragma unroll
        for (int mt = 0; mt < 4; mt++)
#pragma unroll
            for (int nt = 0; nt < 4; nt++)
                mma8(acc[mt][nt], af[mt], bf[nt]);
    }
}

// ----------------------------------------------------------------------------
// Mega layer kernel: one CTA per batch.
//   Mid1 = Z @ aw2^T + ab2 ; att = softmax((aw1@X^T)^T(aw1@X^T)) ;
//   S2   = Mid1 @ att^T    ; (fused node path: X1 = (S2 @ X) @ nw^T + nb)
//   T    = S2 @ Zt^T (Zt = smem transpose of Z) ;
//   Z1   = T @ ew^T + eb  (written to gmem, + edge-BN stats)
// SMEM (floats): sZ[0) sM[REGF) sW[2*REGF) then small arrays.
// ----------------------------------------------------------------------------
#define SM_B1  (3 * REGF)          // 47616: ab2 (128)
#define SM_B2  (SM_B1 + 128)       // eb (128)
#define SM_KS  (SM_B2 + 128)       // Ks (352)
#define SM_XS  (SM_KS + 352)       // X rows (352)
#define SM_PS  (SM_XS + 352)       // edge stat partials (512)
#define SM_PQ  (SM_PS + 512)
#define SM_PA  (SM_PQ + 512)       // node partials 3 x 512
#define SM_TOTF (SM_PA + 1536)
#define SM_TOTB (SM_TOTF * 4)      // ~204 KB

__global__ void __launch_bounds__(256, 1)
k_layer(const float* __restrict__ aw2, const float* __restrict__ ab2,
        const float* __restrict__ aw1, const float* __restrict__ ab1,
        const float* __restrict__ ew,  const float* __restrict__ eb,
        const float* __restrict__ nw,  const float* __restrict__ nb_)
{
    extern __shared__ float sm[];
    float* sZ = sm;
    float* sM = sm + REGF;
    float* sW = sm + 2 * REGF;
    float* sb1 = sm + SM_B1;
    float* sb2 = sm + SM_B2;
    float* sKs = sm + SM_KS;
    float* sXs = sm + SM_XS;
    float* pS  = sm + SM_PS;
    float* pQ  = sm + SM_PQ;
    float* pA  = sm + SM_PA;

    const int tid = threadIdx.x;
    const int b = blockIdx.x;
    const int wid = tid >> 5, lane = tid & 31;
    const int wm = wid >> 2, wn = wid & 3;
    const int g = lane >> 2, tig = lane & 3;
    const float4 z4 = make_float4(0.f, 0.f, 0.f, 0.f);

    // ---- phase 0 ----
    if (tid < 128) {
        sb1[tid] = (tid < R) ? ab2[tid] : 0.f;
        sb2[tid] = (tid < R) ? eb[tid] : 0.f;
    }
    {
        const float* Xb = g_X + (size_t)b * (R * 3);
        for (int i = tid; i < R * 3; i += 256) sXs[i] = Xb[i];
    }
    if (tid < R) {
        const float x0 = sXs[tid * 3], x1 = sXs[tid * 3 + 1], x2 = sXs[tid * 3 + 2];
        // note: sXs may not be fully written by this thread's warp yet; recompute
        // from gmem to be safe:
        const float* xp = g_X + (size_t)b * (R * 3) + tid * 3;
        const float y0 = xp[0], y1 = xp[1], y2 = xp[2];
        (void)x0; (void)x1; (void)x2;
#pragma unroll
        for (int o = 0; o < 3; o++)
            sKs[tid * 3 + o] = fmaf(aw1[o * 3 + 0], y0,
                                fmaf(aw1[o * 3 + 1], y1,
                                fmaf(aw1[o * 3 + 2], y2, ab1[o])));
    }
    // zero pads: rows 116..127 (31 f4) + col 116 f4 (rows 0..115) for all 3 regions
    for (int idx = tid; idx < 3 * 372; idx += 256) {
        const int t = idx / 372, i2 = idx - t * 372;
        const int r = 116 + i2 / 31, c = (i2 - (i2 / 31) * 31) * 4;
        *(float4*)(sm + t * REGF + r * STR + c) = z4;
    }
    for (int idx = tid; idx < 3 * 116; idx += 256) {
        const int t = idx / 116, r = idx - t * 116;
        *(float4*)(sm + t * REGF + r * STR + 116) = z4;
    }
    // load Z -> sZ (tf32), aw2 -> sW (tf32)
    {
        const float* Zb = g_Z + (size_t)b * RR;
        for (int idx = tid; idx < 116 * 29; idx += 256) {
            const int r = idx / 29;
            const int c = (idx - r * 29) << 2;
            const float4 vz = *(const float4*)(Zb + r * R + c);
            float* dz = sZ + r * STR + c;
            dz[0] = to_tf32(vz.x); dz[1] = to_tf32(vz.y);
            dz[2] = to_tf32(vz.z); dz[3] = to_tf32(vz.w);
            const float4 vw = *(const float4*)(aw2 + r * R + c);
            float* dw = sW + r * STR + c;
            dw[0] = to_tf32(vw.x); dw[1] = to_tf32(vw.y);
            dw[2] = to_tf32(vw.z); dw[3] = to_tf32(vw.w);
        }
    }
    __syncthreads();

    float acc[4][4][4];
#pragma unroll
    for (int mt = 0; mt < 4; mt++)
#pragma unroll
        for (int nt = 0; nt < 4; nt++)
#pragma unroll
            for (int i = 0; i < 4; i++) acc[mt][nt][i] = 0.f;

    // ---- GEMM1: Mid1 = Z @ aw2^T ----
    mm_loop(sZ, sW, acc, wm, wn, g, tig);
    __syncthreads();

    // ---- intermediate 1: Mid1+ab2 -> sW ; att -> sM ----
#pragma unroll
    for (int mt = 0; mt < 4; mt++)
#pragma unroll
        for (int h = 0; h < 2; h++) {
            const int row = wm * 64 + mt * 16 + g + 8 * h;
#pragma unroll
            for (int nt = 0; nt < 4; nt++) {
                const int col = wn * 32 + nt * 8 + 2 * tig;
                if (col < 120) {
                    sW[row * STR + col]     = to_tf32(acc[mt][nt][2 * h] + sb1[col]);
                    sW[row * STR + col + 1] = to_tf32(acc[mt][nt][2 * h + 1] + sb1[col + 1]);
                }
            }
        }
    // attention rows: one warp per row n
    for (int n = wid; n < R; n += 8) {
        const float k0 = sKs[n * 3], k1 = sKs[n * 3 + 1], k2 = sKs[n * 3 + 2];
        float s[4];
        float mx = -3.0e38f;
#pragma unroll
        for (int it = 0; it < 4; it++) {
            const int m = it * 32 + lane;
            float v = -3.0e38f;
            if (m < R) v = k0 * sKs[m * 3] + k1 * sKs[m * 3 + 1] + k2 * sKs[m * 3 + 2];
            s[it] = v;
            mx = fmaxf(mx, v);
        }
#pragma unroll
        for (int o = 16; o; o >>= 1) mx = fmaxf(mx, __shfl_xor_sync(0xffffffffu, mx, o));
        float sum = 0.f, e[4];
#pragma unroll
        for (int it = 0; it < 4; it++) {
            const int m = it * 32 + lane;
            e[it] = (m < R) ? __expf(s[it] - mx) : 0.f;
            sum += e[it];
        }
        sum = wsum(sum);
        const float inv = 1.f / sum;
#pragma unroll
        for (int it = 0; it < 4; it++) {
            const int m = it * 32 + lane;
            if (m < R) sM[n * STR + m] = to_tf32(e[it] * inv);
        }
    }
    __syncthreads();

#pragma unroll
    for (int mt = 0; mt < 4; mt++)
#pragma unroll
        for (int nt = 0; nt < 4; nt++)
#pragma unroll
            for (int i = 0; i < 4; i++) acc[mt][nt][i] = 0.f;

    // ---- GEMM2: S2 = Mid1 @ att^T ----
    mm_loop(sW, sM, acc, wm, wn, g, tig);
    __syncthreads();

    // ---- intermediate 2: S2 -> sM ; node partials ; Zt -> sW ; re-zero sW pads ----
#pragma unroll
    for (int mt = 0; mt < 4; mt++)
#pragma unroll
        for (int h = 0; h < 2; h++) {
            const int row = wm * 64 + mt * 16 + g + 8 * h;
            float a0 = 0.f, a1 = 0.f, a2 = 0.f;
#pragma unroll
            for (int nt = 0; nt < 4; nt++) {
                const int col = wn * 32 + nt * 8 + 2 * tig;
                const float v0 = acc[mt][nt][2 * h];
                const float v1 = acc[mt][nt][2 * h + 1];
                if (col < 120) {
                    sM[row * STR + col]     = to_tf32(v0);
                    sM[row * STR + col + 1] = to_tf32(v1);
                }
                if (row < R && col < R) {
                    a0 = fmaf(v0, sXs[col * 3 + 0], fmaf(v1, sXs[col * 3 + 3], a0));
                    a1 = fmaf(v0, sXs[col * 3 + 1], fmaf(v1, sXs[col * 3 + 4], a1));
                    a2 = fmaf(v0, sXs[col * 3 + 2], fmaf(v1, sXs[col * 3 + 5], a2));
                }
            }
            a0 += __shfl_xor_sync(0xffffffffu, a0, 1);
            a0 += __shfl_xor_sync(0xffffffffu, a0, 2);
            a1 += __shfl_xor_sync(0xffffffffu, a1, 1);
            a1 += __shfl_xor_sync(0xffffffffu, a1, 2);
            a2 += __shfl_xor_sync(0xffffffffu, a2, 1);
            a2 += __shfl_xor_sync(0xffffffffu, a2, 2);
            if (tig == 0) {
                pA[0 * 512 + wn * 128 + row] = a0;
                pA[1 * 512 + wn * 128 + row] = a1;
                pA[2 * 512 + wn * 128 + row] = a2;
            }
        }
    // Zt: transpose sZ -> sW (both already tf32)
    for (int idx = tid; idx < 116 * 29; idx += 256) {
        const int r = idx / 29;
        const int c = (idx - r * 29) << 2;
        const float4 v = *(const float4*)(sZ + r * STR + c);
        sW[(c + 0) * STR + r] = v.x;
        sW[(c + 1) * STR + r] = v.y;
        sW[(c + 2) * STR + r] = v.z;
        sW[(c + 3) * STR + r] = v.w;
    }
    // re-zero sW pads (rows 116..127 full, col 116 f4 rows 0..115)
    for (int idx = tid; idx < 372; idx += 256) {
        const int r = 116 + idx / 31, c = (idx - (idx / 31) * 31) * 4;
        *(float4*)(sW + r * STR + c) = z4;
    }
    for (int r = tid; r < 116; r += 256)
        *(float4*)(sW + r * STR + 116) = z4;
    __syncthreads();

#pragma unroll
    for (int mt = 0; mt < 4; mt++)
#pragma unroll
        for (int nt = 0; nt < 4; nt++)
#pragma unroll
            for (int i = 0; i < 4; i++) acc[mt][nt][i] = 0.f;

    // ---- GEMM3: T = S2 @ Zt^T ----
    mm_loop(sM, sW, acc, wm, wn, g, tig);
    __syncthreads();

    // ---- intermediate 3: T -> sM ; ew -> sW ----
#pragma unroll
    for (int mt = 0; mt < 4; mt++)
#pragma unroll
        for (int h = 0; h < 2; h++) {
            const int row = wm * 64 + mt * 16 + g + 8 * h;
#pragma unroll
            for (int nt = 0; nt < 4; nt++) {
                const int col = wn * 32 + nt * 8 + 2 * tig;
                if (col < 120) {
                    sM[row * STR + col]     = to_tf32(acc[mt][nt][2 * h]);
                    sM[row * STR + col + 1] = to_tf32(acc[mt][nt][2 * h + 1]);
                }
            }
        }
    for (int idx = tid; idx < 116 * 29; idx += 256) {
        const int r = idx / 29;
        const int c = (idx - r * 29) << 2;
        const float4 v = *(const float4*)(ew + r * R + c);
        float* d = sW + r * STR + c;
        d[0] = to_tf32(v.x); d[1] = to_tf32(v.y);
        d[2] = to_tf32(v.z); d[3] = to_tf32(v.w);
    }
    __syncthreads();

#pragma unroll
    for (int mt = 0; mt < 4; mt++)
#pragma unroll
        for (int nt = 0; nt < 4; nt++)
#pragma unroll
            for (int i = 0; i < 4; i++) acc[mt][nt][i] = 0.f;

    // ---- GEMM4: Z1 = T @ ew^T + eb ----
    mm_loop(sM, sW, acc, wm, wn, g, tig);

    // ---- epilogue: Z1 + edge stats ----
    float* Cb = g_Z1 + (size_t)b * RR;
#pragma unroll
    for (int mt = 0; mt < 4; mt++) {
#pragma unroll
        for (int h = 0; h < 2; h++) {
            const int row = wm * 64 + mt * 16 + g + 8 * h;
            float s = 0.f, q = 0.f;
#pragma unroll
            for (int nt = 0; nt < 4; nt++) {
                const int col = wn * 32 + nt * 8 + 2 * tig;
                if (col < R) {
                    const float v0 = acc[mt][nt][2 * h] + sb2[col];
                    const float v1 = acc[mt][nt][2 * h + 1] + sb2[col + 1];
                    if (row < R)
                        *(float2*)(Cb + (size_t)row * R + col) = make_float2(v0, v1);
                    s += v0 + v1;
                    q += v0 * v0 + v1 * v1;
                }
            }
            s += __shfl_xor_sync(0xffffffffu, s, 1);
            s += __shfl_xor_sync(0xffffffffu, s, 2);
            q += __shfl_xor_sync(0xffffffffu, q, 1);
            q += __shfl_xor_sync(0xffffffffu, q, 2);
            if (tig == 0) { pS[wn * 128 + row] = s; pQ[wn * 128 + row] = q; }
        }
    }
    __syncthreads();
    if (tid < R) {
        const float s = pS[tid] + pS[128 + tid] + pS[256 + tid] + pS[384 + tid];
        const float q = pQ[tid] + pQ[128 + tid] + pQ[256 + tid] + pQ[384 + tid];
        g_ps[tid * NB + b] = s;
        g_pq[tid * NB + b] = q;
    }
    // ---- node path finish: X1 = (S2 @ X) @ nw^T + nb, node stats ----
    if (tid < R) {
        const int n = tid;
        const float a0 = pA[0 * 512 + n] + pA[0 * 512 + 128 + n] +
                         pA[0 * 512 + 256 + n] + pA[0 * 512 + 384 + n];
        const float a1 = pA[1 * 512 + n] + pA[1 * 512 + 128 + n] +
                         pA[1 * 512 + 256 + n] + pA[1 * 512 + 384 + n];
        const float a2 = pA[2 * 512 + n] + pA[2 * 512 + 128 + n] +
                         pA[2 * 512 + 256 + n] + pA[2 * 512 + 384 + n];
        float ps = 0.f, pq = 0.f;
        float* dst = g_X1 + (size_t)b * (R * 3) + n * 3;
#pragma unroll
        for (int o = 0; o < 3; o++) {
            const float v = fmaf(nw[o * 3 + 0], a0,
                            fmaf(nw[o * 3 + 1], a1,
                            fmaf(nw[o * 3 + 2], a2, nb_[o])));
            dst[o] = v;
            ps += v;
            pq = fmaf(v, v, pq);
        }
        g_psN[n * NB + b] = ps;
        g_pqN[n * NB + b] = pq;
    }
}

// ----------------------------------------------------------------------------
// Both BN channel reductions in one launch. grid = 2R, block = 256.
// ----------------------------------------------------------------------------
__global__ void k_reduce_both(const float* __restrict__ geg, const float* __restrict__ geb,
                              const float* __restrict__ gng, const float* __restrict__ gnb) {
    const bool edge = blockIdx.x < R;
    const int n = edge ? blockIdx.x : blockIdx.x - R;
    const float* PS = edge ? g_ps : g_psN;
    const float* PQ = edge ? g_pq : g_pqN;
    float s = 0.f, q = 0.f;
    for (int b = threadIdx.x; b < NB; b += 256) {
        s += PS[n * NB + b];
        q += PQ[n * NB + b];
    }
    __shared__ float shs[8], shq[8];
    s = wsum(s); q = wsum(q);
    const int w = threadIdx.x >> 5, lane = threadIdx.x & 31;
    if (lane == 0) { shs[w] = s; shq[w] = q; }
    __syncthreads();
    if (w == 0) {
        s = (lane < 8) ? shs[lane] : 0.f;
        q = (lane < 8) ? shq[lane] : 0.f;
        s = wsum(s); q = wsum(q);
        if (lane == 0) {
            const float invcnt = edge ? (1.f / (float)(NB * R)) : (1.f / (float)(3 * NB));
            const float mean = s * invcnt;
            const float var = q * invcnt - mean * mean;
            const float rstd = rsqrtf(var + EPS);
            const float gg = edge ? geg[n] : gng[n];
            const float bb = edge ? geb[n] : gnb[n];
            const float sc = rstd * gg;
            if (edge) { g_scale[n] = sc;  g_shift[n] = bb - mean * sc; }
            else      { g_scaleN[n] = sc; g_shiftN[n] = bb - mean * sc; }
        }
    }
}

// ----------------------------------------------------------------------------
// Combined: Z+=relu(bn(Z1)) & down-edge  /  X+=relu(bn(X1)) & down-node.
// grid = 29696 + 928, block = 128. Raw (unnormalized) features into g_XZ;
// normalization is folded into the classifier via g_dssArr.
// ----------------------------------------------------------------------------
__global__ void k_apply_down(const float* __restrict__ dew, const float* __restrict__ deb,
                             const float* __restrict__ dnw, const float* __restrict__ dnb,
                             int offE, int offN, int dpE, int dpN, int apply) {
    __shared__ float sWt[78];
    __shared__ float sh[8];
    if (blockIdx.x < 29696) {
        // ---------------- edge ----------------
        if (threadIdx.x < 78) sWt[threadIdx.x] = dew[threadIdx.x];
        __syncthreads();
        const int wrp = threadIdx.x >> 5, lane = threadIdx.x & 31;
        const int rowid = blockIdx.x * 4 + wrp;
        const int b = rowid / R, n = rowid - b * R;
        float4 v = make_float4(0.f, 0.f, 0.f, 0.f);
        float* zrow = g_Z + (size_t)rowid * R;
        if (lane < 29) {
            v = *(float4*)(zrow + 4 * lane);
            if (apply) {
                const float4 u = *(const float4*)(g_Z1 + (size_t)rowid * R + 4 * lane);
                const float sc = g_scale[n], sf = g_shift[n];
                v.x += fmaxf(fmaf(u.x, sc, sf), 0.f);
                v.y += fmaxf(fmaf(u.y, sc, sf), 0.f);
                v.z += fmaxf(fmaf(u.z, sc, sf), 0.f);
                v.w += fmaxf(fmaf(u.w, sc, sf), 0.f);
                *(float4*)(zrow + 4 * lane) = v;
            }
        }
        float f0 = 0.f, f1 = 0.f, f2 = 0.f;
        const float vv[4] = {v.x, v.y, v.z, v.w};
#pragma unroll
        for (int d = 0; d < 4; d++) {
            const int e = 4 * lane + d;
            if (e < 78) f1 = fmaf(vv[d], sWt[e], f1);
            if (e < 39) f0 = fmaf(vv[d], sWt[39 + e], f0);
            if (e >= 39 && e < 116) f2 = fmaf(vv[d], sWt[e - 39], f2);
        }
        f0 = wsum(f0); f1 = wsum(f1); f2 = wsum(f2);
        float s = 0.f, q = 0.f;
        if (lane == 0) {
            const float bb = deb[0];
            f0 = fmaxf(f0 + bb, 0.f);
            f1 = fmaxf(f1 + bb, 0.f);
            f2 = fmaxf(f2 + bb, 0.f);
            float* dst = g_XZ + (size_t)b * FEAT + offE + n * 3;
            dst[0] = f0; dst[1] = f1; dst[2] = f2;
            s = f0 + f1 + f2;
            q = f0 * f0 + f1 * f1 + f2 * f2;
            sh[wrp] = s; sh[4 + wrp] = q;
        }
        __syncthreads();
        if (threadIdx.x == 0) {
            g_dpS[dpE + blockIdx.x] = sh[0] + sh[1] + sh[2] + sh[3];
            g_dpQ[dpE + blockIdx.x] = sh[4] + sh[5] + sh[6] + sh[7];
        }
    } else {
        // ---------------- node ----------------
        const int bid = blockIdx.x - 29696;
        const int idx = bid * 128 + threadIdx.x;
        float* xp = g_X + (size_t)idx * 3;
        float x0 = xp[0], x1 = xp[1], x2 = xp[2];
        if (apply) {
            const int n = idx % R;
            const float sc = g_scaleN[n], sf = g_shiftN[n];
            const float* up = g_X1 + (size_t)idx * 3;
            x0 += fmaxf(fmaf(up[0], sc, sf), 0.f);
            x1 += fmaxf(fmaf(up[1], sc, sf), 0.f);
            x2 += fmaxf(fmaf(up[2], sc, sf), 0.f);
            xp[0] = x0; xp[1] = x1; xp[2] = x2;
        }
        const float f = fmaxf(fmaf(x0, dnw[0], fmaf(x1, dnw[1], fmaf(x2, dnw[2], dnb[0]))), 0.f);
        const int b = idx / R, r = idx - (idx / R) * R;
        g_XZ[(size_t)b * FEAT + offN + r] = f;
        const float s = wsum(f);
        const float q = wsum(f * f);
        const int wr = threadIdx.x >> 5, lane = threadIdx.x & 31;
        if (lane == 0) { sh[wr] = s; sh[4 + wr] = q; }
        __syncthreads();
        if (threadIdx.x == 0) {
            g_dpS[dpN + bid] = sh[0] + sh[1] + sh[2] + sh[3];
            g_dpQ[dpN + bid] = sh[4] + sh[5] + sh[6] + sh[7];
        }
    }
}

// ----------------------------------------------------------------------------
// All 10 down-sample reductions at once. grid = 10, block = 1024.
// seg 0..4 = node layer l; seg 5..9 = edge layer l-5.
// ----------------------------------------------------------------------------
__global__ void k_dreduce_all(const float* __restrict__ dng, const float* __restrict__ dnbe,
                              const float* __restrict__ deg, const float* __restrict__ debe) {
    const int sgm = blockIdx.x;
    const bool node = sgm < 5;
    const int l = node ? sgm : sgm - 5;
    const int base = node ? (EDGET + l * 928) : (l * 29696);
    const int cnt = node ? 928 : 29696;
    const float invcnt = node ? (1.f / (float)(NB * R)) : (1.f / (float)(NB * R * 3));
    float s = 0.f, q = 0.f;
    for (int i = threadIdx.x; i < cnt; i += 1024) {
        s += g_dpS[base + i];
        q += g_dpQ[base + i];
    }
    __shared__ float shs[32], shq[32];
    s = wsum(s); q = wsum(q);
    const int w = threadIdx.x >> 5, lane = threadIdx.x & 31;
    if (lane == 0) { shs[w] = s; shq[w] = q; }
    __syncthreads();
    if (w == 0) {
        s = shs[lane]; q = shq[lane];
        s = wsum(s); q = wsum(q);
        if (lane == 0) {
            const float mean = s * invcnt;
            const float var = q * invcnt - mean * mean;
            const float rstd = rsqrtf(var + EPS);
            const float gg = node ? dng[l] : deg[l];
            const float bb = node ? dnbe[l] : debe[l];
            const float sc = rstd * gg;
            g_dssArr[2 * sgm]     = sc;
            g_dssArr[2 * sgm + 1] = bb - mean * sc;
        }
    }
}

// ----------------------------------------------------------------------------
// Classifier GEMM with slab normalization folded into the A-load.
// seg(k) = k/116 for k<580 (node l -> dss pair l), else 5+(k-580)/348.
// ----------------------------------------------------------------------------
__global__ void __launch_bounds__(256)
k_cls(const float* __restrict__ A, const float* __restrict__ Bm,
      const float* __restrict__ bias, float* __restrict__ C)
{
    __shared__ float sA[2][128 * 20];
    __shared__ float sB[2][64 * 20];
    __shared__ float sbc[64];
    const int tid = threadIdx.x;
    const int wid = tid >> 5, lane = tid & 31;
    const int wm = wid >> 1, wn = wid & 1;
    const int g = lane >> 2, tig = lane & 3;
    const int row0 = blockIdx.y * 128, col0 = blockIdx.x * 64;

    if (tid < 64) sbc[tid] = bias[col0 + tid];

    float4 pa0, pa1, pb;
    float fsc, fsh;
    const int ar0 = tid >> 2, ac0 = (tid & 3) << 2;
    const int ar1 = (tid + 256) >> 2, ac1 = ac0;
    const int br = tid >> 2, bc = (tid & 3) << 2;

    auto fetch = [&](int k0) {
        const int k = k0 + ac0;
        const int sgm = (k < 580) ? (k / 116) : (5 + (k - 580) / 348);
        fsc = g_dssArr[2 * sgm];
        fsh = g_dssArr[2 * sgm + 1];
        pa0 = *(const float4*)(A + (size_t)(row0 + ar0) * FEAT + k0 + ac0);
        pa1 = *(const float4*)(A + (size_t)(row0 + ar1) * FEAT + k0 + ac1);
        pb  = *(const float4*)(Bm + (size_t)(col0 + br) * FEAT + k0 + bc);
    };
    auto store = [&](int buf) {
        float* d0 = &sA[buf][ar0 * 20 + ac0];
        d0[0] = to_tf32(fmaf(pa0.x, fsc, fsh)); d0[1] = to_tf32(fmaf(pa0.y, fsc, fsh));
        d0[2] = to_tf32(fmaf(pa0.z, fsc, fsh)); d0[3] = to_tf32(fmaf(pa0.w, fsc, fsh));
        float* d1 = &sA[buf][ar1 * 20 + ac1];
        d1[0] = to_tf32(fmaf(pa1.x, fsc, fsh)); d1[1] = to_tf32(fmaf(pa1.y, fsc, fsh));
        d1[2] = to_tf32(fmaf(pa1.z, fsc, fsh)); d1[3] = to_tf32(fmaf(pa1.w, fsc, fsh));
        float* d2 = &sB[buf][br * 20 + bc];
        d2[0] = to_tf32(pb.x); d2[1] = to_tf32(pb.y);
        d2[2] = to_tf32(pb.z); d2[3] = to_tf32(pb.w);
    };

    float acc[2][4][4];
#pragma unroll
    for (int mt = 0; mt < 2; mt++)
#pragma unroll
        for (int nt = 0; nt < 4; nt++)
#pragma unroll
            for (int i = 0; i < 4; i++) acc[mt][nt][i] = 0.f;

    const int NS = FEAT / 16;
    fetch(0);
    store(0);
    __syncthreads();
    int buf = 0;
    for (int ks = 0; ks < NS; ks++) {
        if (ks + 1 < NS) fetch((ks + 1) * 16);
#pragma unroll
        for (int kk = 0; kk < 2; kk++) {
            const int k0 = kk * 8;
            uint32_t af[2][4], bf[4][2];
#pragma unroll
            for (int mt = 0; mt < 2; mt++) {
                const float* p0 = &sA[buf][(wm * 32 + mt * 16 + g) * 20 + k0 + tig];
                af[mt][0] = __float_as_uint(p0[0]);
                af[mt][1] = __float_as_uint(p0[8 * 20]);
                af[mt][2] = __float_as_uint(p0[4]);
                af[mt][3] = __float_as_uint(p0[8 * 20 + 4]);
            }
#pragma unroll
            for (int nt = 0; nt < 4; nt++) {
                const float* p0 = &sB[buf][(wn * 32 + nt * 8 + g) * 20 + k0 + tig];
                bf[nt][0] = __float_as_uint(p0[0]);
                bf[nt][1] = __float_as_uint(p0[4]);
            }
#pragma unroll
            for (int mt = 0; mt < 2; mt++)
#pragma unroll
                for (int nt = 0; nt < 4; nt++)
                    mma8(acc[mt][nt], af[mt], bf[nt]);
        }
        if (ks + 1 < NS) store(buf ^ 1);
        __syncthreads();
        buf ^= 1;
    }

#pragma unroll
    for (int mt = 0; mt < 2; mt++)
#pragma unroll
        for (int h = 0; h < 2; h++) {
            const int row = row0 + wm * 32 + mt * 16 + g + 8 * h;
#pragma unroll
            for (int nt = 0; nt < 4; nt++) {
                const int col = wn * 32 + nt * 8 + 2 * tig;
                const float v0 = fmaxf(acc[mt][nt][2 * h] + sbc[col], 0.f);
                const float v1 = fmaxf(acc[mt][nt][2 * h + 1] + sbc[col + 1], 0.f);
                *(float2*)(C + (size_t)row * HID + col0 + col) = make_float2(v0, v1);
            }
        }
}

// ----------------------------------------------------------------------------
// Combined input copy (X then Z)
// ----------------------------------------------------------------------------
__global__ void k_copy2(const float* __restrict__ X_in, const float* __restrict__ Z_in) {
    const size_t nX = (size_t)NB * R * 3;
    const size_t nZ = (size_t)NB * RR;
    const size_t i = (size_t)blockIdx.x * blockDim.x + threadIdx.x;
    if (i < nX) g_X[i] = X_in[i];
    else if (i < nX + nZ) g_Z[i - nX] = Z_in[i - nX];
}

__global__ void k_out(const float* __restrict__ cw2, const float* __restrict__ cb2,
                      float* __restrict__ out) {
    const int b = blockIdx.x;
    const float* h = g_H + (size_t)b * HID;
    float a0 = 0.f, a1 = 0.f;
    for (int j = threadIdx.x; j < HID; j += 128) {
        const float hv = h[j];
        a0 = fmaf(hv, cw2[j], a0);
        a1 = fmaf(hv, cw2[HID + j], a1);
    }
    a0 = wsum(a0);
    a1 = wsum(a1);
    __shared__ float sh[8];
    const int w = threadIdx.x >> 5, lane = threadIdx.x & 31;
    if (lane == 0) { sh[w] = a0; sh[4 + w] = a1; }
    __syncthreads();
    if (threadIdx.x == 0) {
        out[b * 2 + 0] = sh[0] + sh[1] + sh[2] + sh[3] + cb2[0];
        out[b * 2 + 1] = sh[4] + sh[5] + sh[6] + sh[7] + cb2[1];
    }
}

// ----------------------------------------------------------------------------
// Host orchestration (graph-capturable: kernel launches only)
// ----------------------------------------------------------------------------
extern "C" void kernel_launch(void* const* d_in, const int* in_sizes, int n_in,
                              void* d_out, int out_size) {
    const float* X_in  = (const float*)d_in[0];
    const float* Z_in  = (const float*)d_in[1];
    const float* aw1   = (const float*)d_in[2];
    const float* ab1   = (const float*)d_in[3];
    const float* aw2   = (const float*)d_in[4];
    const float* ab2   = (const float*)d_in[5];
    const float* nw    = (const float*)d_in[6];
    const float* nb    = (const float*)d_in[7];
    const float* ew    = (const float*)d_in[8];
    const float* eb    = (const float*)d_in[9];
    const float* gn_g  = (const float*)d_in[10];
    const float* gn_b  = (const float*)d_in[11];
    const float* ge_g  = (const float*)d_in[12];
    const float* ge_b  = (const float*)d_in[13];
    const float* dn_w  = (const float*)d_in[14];
    const float* dn_b  = (const float*)d_in[15];
    const float* dn_g  = (const float*)d_in[16];
    const float* dn_be = (const float*)d_in[17];
    const float* de_w  = (const float*)d_in[18];
    const float* de_b  = (const float*)d_in[19];
    const float* de_g  = (const float*)d_in[20];
    const float* de_be = (const float*)d_in[21];
    const float* cw1   = (const float*)d_in[22];
    const float* cb1   = (const float*)d_in[23];
    const float* cw2   = (const float*)d_in[24];
    const float* cb2   = (const float*)d_in[25];
    float* out = (float*)d_out;

    cudaFuncSetAttribute(k_layer, cudaFuncAttributeMaxDynamicSharedMemorySize, SM_TOTB);

    float *pXZ, *pH;
    cudaGetSymbolAddress((void**)&pXZ, g_XZ);
    cudaGetSymbolAddress((void**)&pH,  g_H);

    const size_t tot = (size_t)NB * R * 3 + (size_t)NB * RR;
    k_copy2<<<(unsigned)((tot + 255) / 256), 256>>>(X_in, Z_in);

    // layer-0 down-sample (no BN apply)
    k_apply_down<<<29696 + 928, 128>>>(de_w, de_b, dn_w, dn_b,
                                       580, 0, 0, EDGET, 0);

    for (int i = 0; i < LAYERS; i++) {
        k_layer<<<NB, 256, SM_TOTB>>>(aw2 + (size_t)i * RR, ab2 + i * R,
                                      aw1 + 9 * i, ab1 + 3 * i,
                                      ew + (size_t)i * RR, eb + i * R,
                                      nw + 9 * i, nb + 3 * i);
        k_reduce_both<<<2 * R, 256>>>(ge_g + i * R, ge_b + i * R,
                                      gn_g + i * R, gn_b + i * R);
        const int l = i + 1;
        k_apply_down<<<29696 + 928, 128>>>(de_w + 78 * l, de_b + l,
                                           dn_w + 3 * l, dn_b + l,
                                           580 + l * 348, l * R,
                                           l * 29696, EDGET + l * 928, 1);
    }

    k_dreduce_all<<<10, 1024>>>(dn_g, dn_be, de_g, de_be);
    k_cls<<<dim3(HID / 64, NB / 128), 256>>>(pXZ, cw1, cb1, pH);
    k_out<<<NB, 128>>>(cw2, cb2, out);
}

// round 6
// speedup vs baseline: 3.2035x; 1.2181x over previous
#include <cuda_runtime.h>
#include <cstddef>
#include <cstdint>

// ----------------------------------------------------------------------------
// Problem constants
// ----------------------------------------------------------------------------
#define NB 1024            // batch
#define R 116              // ROIs
#define RR (R * R)         // 13456
#define LAYERS 4
#define FEAT 2320          // R*4*(L+1)
#define HID 1024
#define EPS 1e-5f

#define STR 124            // smem tile row stride (floats)
#define REGF 15872         // floats per 128xSTR tile region
#define EDGET 148480       // 5 * 29696 edge partial slots
#define DPTOT 153120       // + 5 * 928 node slots

// ----------------------------------------------------------------------------
// Device scratch (static allocation only)
// ----------------------------------------------------------------------------
__device__ __align__(16) float g_Z  [(size_t)NB * RR];
__device__ __align__(16) float g_Z1 [(size_t)NB * RR];
__device__ __align__(16) float g_X  [NB * R * 3];
__device__ __align__(16) float g_X1 [NB * R * 3];
__device__ __align__(16) float g_XZ [(size_t)NB * FEAT];
__device__ __align__(16) float g_H  [(size_t)NB * HID];
__device__ float g_ps [R * NB];     // edge BN partials
__device__ float g_pq [R * NB];
__device__ float g_psN[R * NB];     // node BN partials
__device__ float g_pqN[R * NB];
__device__ float g_scale [R],  g_shift [R];   // edge BN affine
__device__ float g_scaleN[R],  g_shiftN[R];   // node BN affine
__device__ float g_dpS[DPTOT], g_dpQ[DPTOT];  // down-sample partials (per layer)
__device__ float g_dssArr[20];                // 10 segments x (scale, shift)

__device__ __forceinline__ float wsum(float v) {
#pragma unroll
    for (int o = 16; o; o >>= 1) v += __shfl_xor_sync(0xffffffffu, v, o);
    return v;
}

__device__ __forceinline__ float to_tf32(float x) {
    float y;
    asm("cvt.rna.tf32.f32 %0, %1;" : "=f"(y) : "f"(x));
    return y;
}

// mma.sync m16n8k8 tf32: d += a (16x8, row) * b (8x8, col)
__device__ __forceinline__ void mma8(float* d, const uint32_t* a, const uint32_t* b) {
    asm volatile(
        "mma.sync.aligned.m16n8k8.row.col.f32.tf32.tf32.f32 "
        "{%0,%1,%2,%3},{%4,%5,%6,%7},{%8,%9},{%0,%1,%2,%3};"
        : "+f"(d[0]), "+f"(d[1]), "+f"(d[2]), "+f"(d[3])
        : "r"(a[0]), "r"(a[1]), "r"(a[2]), "r"(a[3]), "r"(b[0]), "r"(b[1]));
}

// 128x128x120 NT GEMM over whole smem tiles, 16 warps, warp tile 32x32.
__device__ __forceinline__ void mm_loop(const float* __restrict__ sA,
                                        const float* __restrict__ sB,
                                        float (&acc)[2][4][4],
                                        int wm, int wn, int g, int tig) {
#pragma unroll
    for (int ks = 0; ks < 15; ks++) {
        const int k0 = ks * 8;
        uint32_t af[2][4], bf[4][2];
#pragma unroll
        for (int mt = 0; mt < 2; mt++) {
            const float* p0 = sA + (wm * 32 + mt * 16 + g) * STR + k0 + tig;
            af[mt][0] = __float_as_uint(p0[0]);
            af[mt][1] = __float_as_uint(p0[8 * STR]);
            af[mt][2] = __float_as_uint(p0[4]);
            af[mt][3] = __float_as_uint(p0[8 * STR + 4]);
        }
#pragma unroll
        for (int nt = 0; nt < 4; nt++) {
            const float* p0 = sB + (wn * 32 + nt * 8 + g) * STR + k0 + tig;
            bf[nt][0] = __float_as_uint(p0[0]);
            bf[nt][1] = __float_as_uint(p0[4]);
        }
#pragma unroll
        for (int mt = 0; mt < 2; mt++)
#pragma unroll
            for (int nt = 0; nt < 4; nt++)
                mma8(acc[mt][nt], af[mt], bf[nt]);
    }
}

// ----------------------------------------------------------------------------
// Mega layer kernel: one CTA per batch, 512 threads (16 warps, 4x4 grid).
//   Mid1 = Z @ aw2^T + ab2 ; att = softmax((aw1@X^T)^T(aw1@X^T)) ;
//   S2   = Mid1 @ att^T    ; (fused node path: X1 = (S2 @ X) @ nw^T + nb)
//   T    = S2 @ Zt^T (Zt = smem transpose of Z) ;
//   Z1   = T @ ew^T + eb  (written to gmem, + edge-BN stats)
// ----------------------------------------------------------------------------
#define SM_B1  (3 * REGF)          // ab2 (128)
#define SM_B2  (SM_B1 + 128)       // eb (128)
#define SM_KS  (SM_B2 + 128)       // Ks (352)
#define SM_XS  (SM_KS + 352)       // X rows (352)
#define SM_PS  (SM_XS + 352)       // edge stat partials (512)
#define SM_PQ  (SM_PS + 512)
#define SM_PA  (SM_PQ + 512)       // node partials 3 x 512
#define SM_TOTF (SM_PA + 1536)
#define SM_TOTB (SM_TOTF * 4)      // ~204 KB

#define LT 512                     // threads in k_layer

__global__ void __launch_bounds__(LT, 1)
k_layer(const float* __restrict__ aw2, const float* __restrict__ ab2,
        const float* __restrict__ aw1, const float* __restrict__ ab1,
        const float* __restrict__ ew,  const float* __restrict__ eb,
        const float* __restrict__ nw,  const float* __restrict__ nb_)
{
    extern __shared__ float sm[];
    float* sZ = sm;
    float* sM = sm + REGF;
    float* sW = sm + 2 * REGF;
    float* sb1 = sm + SM_B1;
    float* sb2 = sm + SM_B2;
    float* sKs = sm + SM_KS;
    float* sXs = sm + SM_XS;
    float* pS  = sm + SM_PS;
    float* pQ  = sm + SM_PQ;
    float* pA  = sm + SM_PA;

    const int tid = threadIdx.x;
    const int b = blockIdx.x;
    const int wid = tid >> 5, lane = tid & 31;
    const int wm = wid >> 2, wn = wid & 3;
    const int g = lane >> 2, tig = lane & 3;
    const float4 z4 = make_float4(0.f, 0.f, 0.f, 0.f);

    // ---- phase 0 ----
    if (tid < 128) {
        sb1[tid] = (tid < R) ? ab2[tid] : 0.f;
        sb2[tid] = (tid < R) ? eb[tid] : 0.f;
    }
    if (tid < R) {
        const float* xp = g_X + (size_t)b * (R * 3) + tid * 3;
        const float y0 = xp[0], y1 = xp[1], y2 = xp[2];
        sXs[tid * 3 + 0] = y0; sXs[tid * 3 + 1] = y1; sXs[tid * 3 + 2] = y2;
#pragma unroll
        for (int o = 0; o < 3; o++)
            sKs[tid * 3 + o] = fmaf(aw1[o * 3 + 0], y0,
                                fmaf(aw1[o * 3 + 1], y1,
                                fmaf(aw1[o * 3 + 2], y2, ab1[o])));
    }
    // zero pads: rows 116..127 (31 f4) + col 116 f4 (rows 0..115) for all 3 regions
    for (int idx = tid; idx < 3 * 372; idx += LT) {
        const int t = idx / 372, i2 = idx - t * 372;
        const int r = 116 + i2 / 31, c = (i2 - (i2 / 31) * 31) * 4;
        *(float4*)(sm + t * REGF + r * STR + c) = z4;
    }
    for (int idx = tid; idx < 3 * 116; idx += LT) {
        const int t = idx / 116, r = idx - t * 116;
        *(float4*)(sm + t * REGF + r * STR + 116) = z4;
    }
    // load Z -> sZ (tf32), aw2 -> sW (tf32)
    {
        const float* Zb = g_Z + (size_t)b * RR;
        for (int idx = tid; idx < 116 * 29; idx += LT) {
            const int r = idx / 29;
            const int c = (idx - r * 29) << 2;
            const float4 vz = *(const float4*)(Zb + r * R + c);
            float* dz = sZ + r * STR + c;
            dz[0] = to_tf32(vz.x); dz[1] = to_tf32(vz.y);
            dz[2] = to_tf32(vz.z); dz[3] = to_tf32(vz.w);
            const float4 vw = *(const float4*)(aw2 + r * R + c);
            float* dw = sW + r * STR + c;
            dw[0] = to_tf32(vw.x); dw[1] = to_tf32(vw.y);
            dw[2] = to_tf32(vw.z); dw[3] = to_tf32(vw.w);
        }
    }
    __syncthreads();

    float acc[2][4][4];
#pragma unroll
    for (int mt = 0; mt < 2; mt++)
#pragma unroll
        for (int nt = 0; nt < 4; nt++)
#pragma unroll
            for (int i = 0; i < 4; i++) acc[mt][nt][i] = 0.f;

    // ---- GEMM1: Mid1 = Z @ aw2^T ----
    mm_loop(sZ, sW, acc, wm, wn, g, tig);
    __syncthreads();

    // ---- intermediate 1: Mid1+ab2 -> sW ; att -> sM ----
#pragma unroll
    for (int mt = 0; mt < 2; mt++)
#pragma unroll
        for (int h = 0; h < 2; h++) {
            const int row = wm * 32 + mt * 16 + g + 8 * h;
#pragma unroll
            for (int nt = 0; nt < 4; nt++) {
                const int col = wn * 32 + nt * 8 + 2 * tig;
                if (col < 120) {
                    sW[row * STR + col]     = to_tf32(acc[mt][nt][2 * h] + sb1[col]);
                    sW[row * STR + col + 1] = to_tf32(acc[mt][nt][2 * h + 1] + sb1[col + 1]);
                }
            }
        }
    // attention rows: one warp per row n
    for (int n = wid; n < R; n += 16) {
        const float k0 = sKs[n * 3], k1 = sKs[n * 3 + 1], k2 = sKs[n * 3 + 2];
        float s[4];
        float mx = -3.0e38f;
#pragma unroll
        for (int it = 0; it < 4; it++) {
            const int m = it * 32 + lane;
            float v = -3.0e38f;
            if (m < R) v = k0 * sKs[m * 3] + k1 * sKs[m * 3 + 1] + k2 * sKs[m * 3 + 2];
            s[it] = v;
            mx = fmaxf(mx, v);
        }
#pragma unroll
        for (int o = 16; o; o >>= 1) mx = fmaxf(mx, __shfl_xor_sync(0xffffffffu, mx, o));
        float sum = 0.f, e[4];
#pragma unroll
        for (int it = 0; it < 4; it++) {
            const int m = it * 32 + lane;
            e[it] = (m < R) ? __expf(s[it] - mx) : 0.f;
            sum += e[it];
        }
        sum = wsum(sum);
        const float inv = 1.f / sum;
#pragma unroll
        for (int it = 0; it < 4; it++) {
            const int m = it * 32 + lane;
            if (m < R) sM[n * STR + m] = to_tf32(e[it] * inv);
        }
    }
    __syncthreads();

#pragma unroll
    for (int mt = 0; mt < 2; mt++)
#pragma unroll
        for (int nt = 0; nt < 4; nt++)
#pragma unroll
            for (int i = 0; i < 4; i++) acc[mt][nt][i] = 0.f;

    // ---- GEMM2: S2 = Mid1 @ att^T ----
    mm_loop(sW, sM, acc, wm, wn, g, tig);
    __syncthreads();

    // ---- intermediate 2: S2 -> sM ; node partials ; Zt -> sW ; re-zero sW pads ----
#pragma unroll
    for (int mt = 0; mt < 2; mt++)
#pragma unroll
        for (int h = 0; h < 2; h++) {
            const int row = wm * 32 + mt * 16 + g + 8 * h;
            float a0 = 0.f, a1 = 0.f, a2 = 0.f;
#pragma unroll
            for (int nt = 0; nt < 4; nt++) {
                const int col = wn * 32 + nt * 8 + 2 * tig;
                const float v0 = acc[mt][nt][2 * h];
                const float v1 = acc[mt][nt][2 * h + 1];
                if (col < 120) {
                    sM[row * STR + col]     = to_tf32(v0);
                    sM[row * STR + col + 1] = to_tf32(v1);
                }
                if (row < R && col < R) {
                    a0 = fmaf(v0, sXs[col * 3 + 0], fmaf(v1, sXs[col * 3 + 3], a0));
                    a1 = fmaf(v0, sXs[col * 3 + 1], fmaf(v1, sXs[col * 3 + 4], a1));
                    a2 = fmaf(v0, sXs[col * 3 + 2], fmaf(v1, sXs[col * 3 + 5], a2));
                }
            }
            a0 += __shfl_xor_sync(0xffffffffu, a0, 1);
            a0 += __shfl_xor_sync(0xffffffffu, a0, 2);
            a1 += __shfl_xor_sync(0xffffffffu, a1, 1);
            a1 += __shfl_xor_sync(0xffffffffu, a1, 2);
            a2 += __shfl_xor_sync(0xffffffffu, a2, 1);
            a2 += __shfl_xor_sync(0xffffffffu, a2, 2);
            if (tig == 0) {
                pA[0 * 512 + wn * 128 + row] = a0;
                pA[1 * 512 + wn * 128 + row] = a1;
                pA[2 * 512 + wn * 128 + row] = a2;
            }
        }
    // Zt: transpose sZ -> sW (both already tf32)
    for (int idx = tid; idx < 116 * 29; idx += LT) {
        const int r = idx / 29;
        const int c = (idx - r * 29) << 2;
        const float4 v = *(const float4*)(sZ + r * STR + c);
        sW[(c + 0) * STR + r] = v.x;
        sW[(c + 1) * STR + r] = v.y;
        sW[(c + 2) * STR + r] = v.z;
        sW[(c + 3) * STR + r] = v.w;
    }
    // re-zero sW pads
    for (int idx = tid; idx < 372; idx += LT) {
        const int r = 116 + idx / 31, c = (idx - (idx / 31) * 31) * 4;
        *(float4*)(sW + r * STR + c) = z4;
    }
    for (int r = tid; r < 116; r += LT)
        *(float4*)(sW + r * STR + 116) = z4;
    __syncthreads();

#pragma unroll
    for (int mt = 0; mt < 2; mt++)
#pragma unroll
        for (int nt = 0; nt < 4; nt++)
#pragma unroll
            for (int i = 0; i < 4; i++) acc[mt][nt][i] = 0.f;

    // ---- GEMM3: T = S2 @ Zt^T ----
    mm_loop(sM, sW, acc, wm, wn, g, tig);
    __syncthreads();

    // ---- intermediate 3: T -> sM ; ew -> sW ----
#pragma unroll
    for (int mt = 0; mt < 2; mt++)
#pragma unroll
        for (int h = 0; h < 2; h++) {
            const int row = wm * 32 + mt * 16 + g + 8 * h;
#pragma unroll
            for (int nt = 0; nt < 4; nt++) {
                const int col = wn * 32 + nt * 8 + 2 * tig;
                if (col < 120) {
                    sM[row * STR + col]     = to_tf32(acc[mt][nt][2 * h]);
                    sM[row * STR + col + 1] = to_tf32(acc[mt][nt][2 * h + 1]);
                }
            }
        }
    for (int idx = tid; idx < 116 * 29; idx += LT) {
        const int r = idx / 29;
        const int c = (idx - r * 29) << 2;
        const float4 v = *(const float4*)(ew + r * R + c);
        float* d = sW + r * STR + c;
        d[0] = to_tf32(v.x); d[1] = to_tf32(v.y);
        d[2] = to_tf32(v.z); d[3] = to_tf32(v.w);
    }
    __syncthreads();

#pragma unroll
    for (int mt = 0; mt < 2; mt++)
#pragma unroll
        for (int nt = 0; nt < 4; nt++)
#pragma unroll
            for (int i = 0; i < 4; i++) acc[mt][nt][i] = 0.f;

    // ---- GEMM4: Z1 = T @ ew^T + eb ----
    mm_loop(sM, sW, acc, wm, wn, g, tig);

    // ---- epilogue: Z1 + edge stats ----
    float* Cb = g_Z1 + (size_t)b * RR;
#pragma unroll
    for (int mt = 0; mt < 2; mt++) {
#pragma unroll
        for (int h = 0; h < 2; h++) {
            const int row = wm * 32 + mt * 16 + g + 8 * h;
            float s = 0.f, q = 0.f;
#pragma unroll
            for (int nt = 0; nt < 4; nt++) {
                const int col = wn * 32 + nt * 8 + 2 * tig;
                if (col < R) {
                    const float v0 = acc[mt][nt][2 * h] + sb2[col];
                    const float v1 = acc[mt][nt][2 * h + 1] + sb2[col + 1];
                    if (row < R)
                        *(float2*)(Cb + (size_t)row * R + col) = make_float2(v0, v1);
                    s += v0 + v1;
                    q += v0 * v0 + v1 * v1;
                }
            }
            s += __shfl_xor_sync(0xffffffffu, s, 1);
            s += __shfl_xor_sync(0xffffffffu, s, 2);
            q += __shfl_xor_sync(0xffffffffu, q, 1);
            q += __shfl_xor_sync(0xffffffffu, q, 2);
            if (tig == 0) { pS[wn * 128 + row] = s; pQ[wn * 128 + row] = q; }
        }
    }
    __syncthreads();
    if (tid < R) {
        const float s = pS[tid] + pS[128 + tid] + pS[256 + tid] + pS[384 + tid];
        const float q = pQ[tid] + pQ[128 + tid] + pQ[256 + tid] + pQ[384 + tid];
        g_ps[tid * NB + b] = s;
        g_pq[tid * NB + b] = q;
    }
    // ---- node path finish: X1 = (S2 @ X) @ nw^T + nb, node stats ----
    if (tid < R) {
        const int n = tid;
        const float a0 = pA[0 * 512 + n] + pA[0 * 512 + 128 + n] +
                         pA[0 * 512 + 256 + n] + pA[0 * 512 + 384 + n];
        const float a1 = pA[1 * 512 + n] + pA[1 * 512 + 128 + n] +
                         pA[1 * 512 + 256 + n] + pA[1 * 512 + 384 + n];
        const float a2 = pA[2 * 512 + n] + pA[2 * 512 + 128 + n] +
                         pA[2 * 512 + 256 + n] + pA[2 * 512 + 384 + n];
        float ps = 0.f, pq = 0.f;
        float* dst = g_X1 + (size_t)b * (R * 3) + n * 3;
#pragma unroll
        for (int o = 0; o < 3; o++) {
            const float v = fmaf(nw[o * 3 + 0], a0,
                            fmaf(nw[o * 3 + 1], a1,
                            fmaf(nw[o * 3 + 2], a2, nb_[o])));
            dst[o] = v;
            ps += v;
            pq = fmaf(v, v, pq);
        }
        g_psN[n * NB + b] = ps;
        g_pqN[n * NB + b] = pq;
    }
}

// ----------------------------------------------------------------------------
// Both BN channel reductions in one launch. grid = 2R, block = 256.
// ----------------------------------------------------------------------------
__global__ void k_reduce_both(const float* __restrict__ geg, const float* __restrict__ geb,
                              const float* __restrict__ gng, const float* __restrict__ gnb) {
    const bool edge = blockIdx.x < R;
    const int n = edge ? blockIdx.x : blockIdx.x - R;
    const float* PS = edge ? g_ps : g_psN;
    const float* PQ = edge ? g_pq : g_pqN;
    float s = 0.f, q = 0.f;
    for (int b = threadIdx.x; b < NB; b += 256) {
        s += PS[n * NB + b];
        q += PQ[n * NB + b];
    }
    __shared__ float shs[8], shq[8];
    s = wsum(s); q = wsum(q);
    const int w = threadIdx.x >> 5, lane = threadIdx.x & 31;
    if (lane == 0) { shs[w] = s; shq[w] = q; }
    __syncthreads();
    if (w == 0) {
        s = (lane < 8) ? shs[lane] : 0.f;
        q = (lane < 8) ? shq[lane] : 0.f;
        s = wsum(s); q = wsum(q);
        if (lane == 0) {
            const float invcnt = edge ? (1.f / (float)(NB * R)) : (1.f / (float)(3 * NB));
            const float mean = s * invcnt;
            const float var = q * invcnt - mean * mean;
            const float rstd = rsqrtf(var + EPS);
            const float gg = edge ? geg[n] : gng[n];
            const float bb = edge ? geb[n] : gnb[n];
            const float sc = rstd * gg;
            if (edge) { g_scale[n] = sc;  g_shift[n] = bb - mean * sc; }
            else      { g_scaleN[n] = sc; g_shiftN[n] = bb - mean * sc; }
        }
    }
}

// ----------------------------------------------------------------------------
// Combined: Z+=relu(bn(Z1)) & down-edge  /  X+=relu(bn(X1)) & down-node.
// apply==0: pass-through copy from srcZ/srcX into g_Z/g_X (layer 0).
// grid = 29696 + 928, block = 128.
// ----------------------------------------------------------------------------
__global__ void k_apply_down(const float* __restrict__ dew, const float* __restrict__ deb,
                             const float* __restrict__ dnw, const float* __restrict__ dnb,
                             const float* __restrict__ srcZ, const float* __restrict__ srcX,
                             int offE, int offN, int dpE, int dpN, int apply) {
    __shared__ float sWt[78];
    __shared__ float sh[8];
    if (blockIdx.x < 29696) {
        // ---------------- edge ----------------
        if (threadIdx.x < 78) sWt[threadIdx.x] = dew[threadIdx.x];
        __syncthreads();
        const int wrp = threadIdx.x >> 5, lane = threadIdx.x & 31;
        const int rowid = blockIdx.x * 4 + wrp;
        const int b = rowid / R, n = rowid - b * R;
        float4 v = make_float4(0.f, 0.f, 0.f, 0.f);
        float* zrow = g_Z + (size_t)rowid * R;
        if (lane < 29) {
            if (apply) {
                v = *(float4*)(zrow + 4 * lane);
                const float4 u = *(const float4*)(g_Z1 + (size_t)rowid * R + 4 * lane);
                const float sc = g_scale[n], sf = g_shift[n];
                v.x += fmaxf(fmaf(u.x, sc, sf), 0.f);
                v.y += fmaxf(fmaf(u.y, sc, sf), 0.f);
                v.z += fmaxf(fmaf(u.z, sc, sf), 0.f);
                v.w += fmaxf(fmaf(u.w, sc, sf), 0.f);
                *(float4*)(zrow + 4 * lane) = v;
            } else {
                v = *(const float4*)(srcZ + (size_t)rowid * R + 4 * lane);
                *(float4*)(zrow + 4 * lane) = v;
            }
        }
        float f0 = 0.f, f1 = 0.f, f2 = 0.f;
        const float vv[4] = {v.x, v.y, v.z, v.w};
#pragma unroll
        for (int d = 0; d < 4; d++) {
            const int e = 4 * lane + d;
            if (e < 78) f1 = fmaf(vv[d], sWt[e], f1);
            if (e < 39) f0 = fmaf(vv[d], sWt[39 + e], f0);
            if (e >= 39 && e < 116) f2 = fmaf(vv[d], sWt[e - 39], f2);
        }
        f0 = wsum(f0); f1 = wsum(f1); f2 = wsum(f2);
        float s = 0.f, q = 0.f;
        if (lane == 0) {
            const float bb = deb[0];
            f0 = fmaxf(f0 + bb, 0.f);
            f1 = fmaxf(f1 + bb, 0.f);
            f2 = fmaxf(f2 + bb, 0.f);
            float* dst = g_XZ + (size_t)b * FEAT + offE + n * 3;
            dst[0] = f0; dst[1] = f1; dst[2] = f2;
            s = f0 + f1 + f2;
            q = f0 * f0 + f1 * f1 + f2 * f2;
            sh[wrp] = s; sh[4 + wrp] = q;
        }
        __syncthreads();
        if (threadIdx.x == 0) {
            g_dpS[dpE + blockIdx.x] = sh[0] + sh[1] + sh[2] + sh[3];
            g_dpQ[dpE + blockIdx.x] = sh[4] + sh[5] + sh[6] + sh[7];
        }
    } else {
        // ---------------- node ----------------
        const int bid = blockIdx.x - 29696;
        const int idx = bid * 128 + threadIdx.x;
        float* xp = g_X + (size_t)idx * 3;
        float x0, x1, x2;
        if (apply) {
            x0 = xp[0]; x1 = xp[1]; x2 = xp[2];
            const int n = idx % R;
            const float sc = g_scaleN[n], sf = g_shiftN[n];
            const float* up = g_X1 + (size_t)idx * 3;
            x0 += fmaxf(fmaf(up[0], sc, sf), 0.f);
            x1 += fmaxf(fmaf(up[1], sc, sf), 0.f);
            x2 += fmaxf(fmaf(up[2], sc, sf), 0.f);
            xp[0] = x0; xp[1] = x1; xp[2] = x2;
        } else {
            const float* sp = srcX + (size_t)idx * 3;
            x0 = sp[0]; x1 = sp[1]; x2 = sp[2];
            xp[0] = x0; xp[1] = x1; xp[2] = x2;
        }
        const float f = fmaxf(fmaf(x0, dnw[0], fmaf(x1, dnw[1], fmaf(x2, dnw[2], dnb[0]))), 0.f);
        const int b = idx / R, r = idx - (idx / R) * R;
        g_XZ[(size_t)b * FEAT + offN + r] = f;
        const float s = wsum(f);
        const float q = wsum(f * f);
        const int wr = threadIdx.x >> 5, lane = threadIdx.x & 31;
        if (lane == 0) { sh[wr] = s; sh[4 + wr] = q; }
        __syncthreads();
        if (threadIdx.x == 0) {
            g_dpS[dpN + bid] = sh[0] + sh[1] + sh[2] + sh[3];
            g_dpQ[dpN + bid] = sh[4] + sh[5] + sh[6] + sh[7];
        }
    }
}

// ----------------------------------------------------------------------------
// All 10 down-sample reductions at once. grid = 10, block = 1024.
// ----------------------------------------------------------------------------
__global__ void k_dreduce_all(const float* __restrict__ dng, const float* __restrict__ dnbe,
                              const float* __restrict__ deg, const float* __restrict__ debe) {
    const int sgm = blockIdx.x;
    const bool node = sgm < 5;
    const int l = node ? sgm : sgm - 5;
    const int base = node ? (EDGET + l * 928) : (l * 29696);
    const int cnt = node ? 928 : 29696;
    const float invcnt = node ? (1.f / (float)(NB * R)) : (1.f / (float)(NB * R * 3));
    float s = 0.f, q = 0.f;
    for (int i = threadIdx.x; i < cnt; i += 1024) {
        s += g_dpS[base + i];
        q += g_dpQ[base + i];
    }
    __shared__ float shs[32], shq[32];
    s = wsum(s); q = wsum(q);
    const int w = threadIdx.x >> 5, lane = threadIdx.x & 31;
    if (lane == 0) { shs[w] = s; shq[w] = q; }
    __syncthreads();
    if (w == 0) {
        s = shs[lane]; q = shq[lane];
        s = wsum(s); q = wsum(q);
        if (lane == 0) {
            const float mean = s * invcnt;
            const float var = q * invcnt - mean * mean;
            const float rstd = rsqrtf(var + EPS);
            const float gg = node ? dng[l] : deg[l];
            const float bb = node ? dnbe[l] : debe[l];
            const float sc = rstd * gg;
            g_dssArr[2 * sgm]     = sc;
            g_dssArr[2 * sgm + 1] = bb - mean * sc;
        }
    }
}

// ----------------------------------------------------------------------------
// Classifier GEMM with slab normalization folded into the A-load.
// ----------------------------------------------------------------------------
__global__ void __launch_bounds__(256)
k_cls(const float* __restrict__ A, const float* __restrict__ Bm,
      const float* __restrict__ bias, float* __restrict__ C)
{
    __shared__ float sA[2][128 * 20];
    __shared__ float sB[2][64 * 20];
    __shared__ float sbc[64];
    const int tid = threadIdx.x;
    const int wid = tid >> 5, lane = tid & 31;
    const int wm = wid >> 1, wn = wid & 1;
    const int g = lane >> 2, tig = lane & 3;
    const int row0 = blockIdx.y * 128, col0 = blockIdx.x * 64;

    if (tid < 64) sbc[tid] = bias[col0 + tid];

    float4 pa0, pa1, pb;
    float fsc, fsh;
    const int ar0 = tid >> 2, ac0 = (tid & 3) << 2;
    const int ar1 = (tid + 256) >> 2, ac1 = ac0;
    const int br = tid >> 2, bc = (tid & 3) << 2;

    auto fetch = [&](int k0) {
        const int k = k0 + ac0;
        const int sgm = (k < 580) ? (k / 116) : (5 + (k - 580) / 348);
        fsc = g_dssArr[2 * sgm];
        fsh = g_dssArr[2 * sgm + 1];
        pa0 = *(const float4*)(A + (size_t)(row0 + ar0) * FEAT + k0 + ac0);
        pa1 = *(const float4*)(A + (size_t)(row0 + ar1) * FEAT + k0 + ac1);
        pb  = *(const float4*)(Bm + (size_t)(col0 + br) * FEAT + k0 + bc);
    };
    auto store = [&](int buf) {
        float* d0 = &sA[buf][ar0 * 20 + ac0];
        d0[0] = to_tf32(fmaf(pa0.x, fsc, fsh)); d0[1] = to_tf32(fmaf(pa0.y, fsc, fsh));
        d0[2] = to_tf32(fmaf(pa0.z, fsc, fsh)); d0[3] = to_tf32(fmaf(pa0.w, fsc, fsh));
        float* d1 = &sA[buf][ar1 * 20 + ac1];
        d1[0] = to_tf32(fmaf(pa1.x, fsc, fsh)); d1[1] = to_tf32(fmaf(pa1.y, fsc, fsh));
        d1[2] = to_tf32(fmaf(pa1.z, fsc, fsh)); d1[3] = to_tf32(fmaf(pa1.w, fsc, fsh));
        float* d2 = &sB[buf][br * 20 + bc];
        d2[0] = to_tf32(pb.x); d2[1] = to_tf32(pb.y);
        d2[2] = to_tf32(pb.z); d2[3] = to_tf32(pb.w);
    };

    float acc[2][4][4];
#pragma unroll
    for (int mt = 0; mt < 2; mt++)
#pragma unroll
        for (int nt = 0; nt < 4; nt++)
#pragma unroll
            for (int i = 0; i < 4; i++) acc[mt][nt][i] = 0.f;

    const int NS = FEAT / 16;
    fetch(0);
    store(0);
    __syncthreads();
    int buf = 0;
    for (int ks = 0; ks < NS; ks++) {
        if (ks + 1 < NS) fetch((ks + 1) * 16);
#pragma unroll
        for (int kk = 0; kk < 2; kk++) {
            const int k0 = kk * 8;
            uint32_t af[2][4], bf[4][2];
#pragma unroll
            for (int mt = 0; mt < 2; mt++) {
                const float* p0 = &sA[buf][(wm * 32 + mt * 16 + g) * 20 + k0 + tig];
                af[mt][0] = __float_as_uint(p0[0]);
                af[mt][1] = __float_as_uint(p0[8 * 20]);
                af[mt][2] = __float_as_uint(p0[4]);
                af[mt][3] = __float_as_uint(p0[8 * 20 + 4]);
            }
#pragma unroll
            for (int nt = 0; nt < 4; nt++) {
                const float* p0 = &sB[buf][(wn * 32 + nt * 8 + g) * 20 + k0 + tig];
                bf[nt][0] = __float_as_uint(p0[0]);
                bf[nt][1] = __float_as_uint(p0[4]);
            }
#pragma unroll
            for (int mt = 0; mt < 2; mt++)
#pragma unroll
                for (int nt = 0; nt < 4; nt++)
                    mma8(acc[mt][nt], af[mt], bf[nt]);
        }
        if (ks + 1 < NS) store(buf ^ 1);
        __syncthreads();
        buf ^= 1;
    }

#pragma unroll
    for (int mt = 0; mt < 2; mt++)
#pragma unroll
        for (int h = 0; h < 2; h++) {
            const int row = row0 + wm * 32 + mt * 16 + g + 8 * h;
#pragma unroll
            for (int nt = 0; nt < 4; nt++) {
                const int col = wn * 32 + nt * 8 + 2 * tig;
                const float v0 = fmaxf(acc[mt][nt][2 * h] + sbc[col], 0.f);
                const float v1 = fmaxf(acc[mt][nt][2 * h + 1] + sbc[col + 1], 0.f);
                *(float2*)(C + (size_t)row * HID + col0 + col) = make_float2(v0, v1);
            }
        }
}

__global__ void k_out(const float* __restrict__ cw2, const float* __restrict__ cb2,
                      float* __restrict__ out) {
    const int b = blockIdx.x;
    const float* h = g_H + (size_t)b * HID;
    float a0 = 0.f, a1 = 0.f;
    for (int j = threadIdx.x; j < HID; j += 128) {
        const float hv = h[j];
        a0 = fmaf(hv, cw2[j], a0);
        a1 = fmaf(hv, cw2[HID + j], a1);
    }
    a0 = wsum(a0);
    a1 = wsum(a1);
    __shared__ float sh[8];
    const int w = threadIdx.x >> 5, lane = threadIdx.x & 31;
    if (lane == 0) { sh[w] = a0; sh[4 + w] = a1; }
    __syncthreads();
    if (threadIdx.x == 0) {
        out[b * 2 + 0] = sh[0] + sh[1] + sh[2] + sh[3] + cb2[0];
        out[b * 2 + 1] = sh[4] + sh[5] + sh[6] + sh[7] + cb2[1];
    }
}

// ----------------------------------------------------------------------------
// Host orchestration (graph-capturable: kernel launches only)
// ----------------------------------------------------------------------------
extern "C" void kernel_launch(void* const* d_in, const int* in_sizes, int n_in,
                              void* d_out, int out_size) {
    const float* X_in  = (const float*)d_in[0];
    const float* Z_in  = (const float*)d_in[1];
    const float* aw1   = (const float*)d_in[2];
    const float* ab1   = (const float*)d_in[3];
    const float* aw2   = (const float*)d_in[4];
    const float* ab2   = (const float*)d_in[5];
    const float* nw    = (const float*)d_in[6];
    const float* nb    = (const float*)d_in[7];
    const float* ew    = (const float*)d_in[8];
    const float* eb    = (const float*)d_in[9];
    const float* gn_g  = (const float*)d_in[10];
    const float* gn_b  = (const float*)d_in[11];
    const float* ge_g  = (const float*)d_in[12];
    const float* ge_b  = (const float*)d_in[13];
    const float* dn_w  = (const float*)d_in[14];
    const float* dn_b  = (const float*)d_in[15];
    const float* dn_g  = (const float*)d_in[16];
    const float* dn_be = (const float*)d_in[17];
    const float* de_w  = (const float*)d_in[18];
    const float* de_b  = (const float*)d_in[19];
    const float* de_g  = (const float*)d_in[20];
    const float* de_be = (const float*)d_in[21];
    const float* cw1   = (const float*)d_in[22];
    const float* cb1   = (const float*)d_in[23];
    const float* cw2   = (const float*)d_in[24];
    const float* cb2   = (const float*)d_in[25];
    float* out = (float*)d_out;

    cudaFuncSetAttribute(k_layer, cudaFuncAttributeMaxDynamicSharedMemorySize, SM_TOTB);

    float *pXZ, *pH;
    cudaGetSymbolAddress((void**)&pXZ, g_XZ);
    cudaGetSymbolAddress((void**)&pH,  g_H);

    // layer-0 down-sample, fused with input pass-through copy
    k_apply_down<<<29696 + 928, 128>>>(de_w, de_b, dn_w, dn_b,
                                       Z_in, X_in,
                                       580, 0, 0, EDGET, 0);

    for (int i = 0; i < LAYERS; i++) {
        k_layer<<<NB, LT, SM_TOTB>>>(aw2 + (size_t)i * RR, ab2 + i * R,
                                     aw1 + 9 * i, ab1 + 3 * i,
                                     ew + (size_t)i * RR, eb + i * R,
                                     nw + 9 * i, nb + 3 * i);
        k_reduce_both<<<2 * R, 256>>>(ge_g + i * R, ge_b + i * R,
                                      gn_g + i * R, gn_b + i * R);
        const int l = i + 1;
        k_apply_down<<<29696 + 928, 128>>>(de_w + 78 * l, de_b + l,
                                           dn_w + 3 * l, dn_b + l,
                                           nullptr, nullptr,
                                           580 + l * 348, l * R,
                                           l * 29696, EDGET + l * 928, 1);
    }

    k_dreduce_all<<<10, 1024>>>(dn_g, dn_be, de_g, de_be);
    k_cls<<<dim3(HID / 64, NB / 128), 256>>>(pXZ, cw1, cb1, pH);
    k_out<<<NB, 128>>>(cw2, cb2, out);
}